// round 14
// baseline (speedup 1.0000x reference)
#include <cuda_runtime.h>
#include <cuda_fp16.h>
#include <stdint.h>

#define Bsz 4
#define Sq  4096
#define Dd  1024
#define BS  (Bsz * Sq)   // 16384

// ---------------- scratch (device globals — allocation is forbidden) ----------------
__device__ __align__(256) __half g_xh[(long long)BS * Dd];          // x fp16 [t][d]
__device__ __align__(256) __half g_xTh[(long long)BS * Dd];         // x^T fp16 [b][d][t]
__device__ __align__(256) __half g_Gh[(long long)Bsz * Dd * Dd];    // Gram fp16 [b][e][e']
__device__ __align__(256) float  g_WkHat[(long long)Dd * 1026];     // [e][Re 513 | Im 513]
__device__ __align__(256) __half g_WvHatT[(long long)1152 * Dd];    // [f-comp][e], rows 0-512 Re, 513-1025 Im
__device__ __align__(256) float  g_bhat[2 * 1026];                  // bk-hat, bv-hat
__device__ __align__(256) float  g_Y[(long long)Bsz * Dd * 1152];   // G @ WvHat (fp32)
__device__ __align__(256) float  g_m[Bsz * Dd];
__device__ __align__(256) float  g_mk[Bsz * Dd];
__device__ __align__(256) float  g_mv[Bsz * Dd];
__device__ __align__(256) float  g_S[Bsz * 513 * 2];
__device__ __align__(256) float  g_r[Bsz * Dd];
__device__ __align__(256) __half g_W2tmp[(long long)Bsz * Dd * Dd]; // [b][d][n]
__device__ __align__(256) __half g_W2Ts[(long long)Bsz * Dd * Dd];  // [b][n][d]

// ---------------- PTX helpers ----------------
__device__ __forceinline__ uint32_t smem_u32(const void* p) {
    uint32_t a;
    asm("{ .reg .u64 t; cvta.to.shared.u64 t, %1; cvt.u32.u64 %0, t; }" : "=r"(a) : "l"(p));
    return a;
}
__device__ __forceinline__ void cp16(uint32_t dst, const void* src) {
    asm volatile("cp.async.cg.shared.global [%0], [%1], 16;" :: "r"(dst), "l"(src));
}
__device__ __forceinline__ void cp_commit() { asm volatile("cp.async.commit_group;" ::: "memory"); }
template<int N> __device__ __forceinline__ void cp_wait() {
    asm volatile("cp.async.wait_group %0;" :: "n"(N) : "memory");
}

__device__ __forceinline__ void ldsm_x4(uint32_t& r0, uint32_t& r1, uint32_t& r2, uint32_t& r3,
                                        uint32_t addr) {
    asm volatile("ldmatrix.sync.aligned.m8n8.x4.shared.b16 {%0,%1,%2,%3}, [%4];"
                 : "=r"(r0), "=r"(r1), "=r"(r2), "=r"(r3) : "r"(addr));
}
__device__ __forceinline__ void mma_fp16(float& c0, float& c1, float& c2, float& c3,
                                         uint32_t a0, uint32_t a1, uint32_t a2, uint32_t a3,
                                         uint32_t b0, uint32_t b1) {
    asm volatile(
        "mma.sync.aligned.m16n8k16.row.col.f32.f16.f16.f32 "
        "{%0,%1,%2,%3}, {%4,%5,%6,%7}, {%8,%9}, {%0,%1,%2,%3};"
        : "+f"(c0), "+f"(c1), "+f"(c2), "+f"(c3)
        : "r"(a0), "r"(a1), "r"(a2), "r"(a3), "r"(b0), "r"(b1));
}

// ---------------- fp16 HMMA GEMM: C[M,N] = Ah @ Bs^T (+bias[n]) ----------------
// CTA tile 128x128x64, 128 threads = 4 warps (2x2), warp tile 64x64, 2 CTAs/SM.
// 3-stage cp.async ring, one __syncthreads per chunk, fragment double-buffering.
#define STG1 32768
#define DSMEM1 (3 * STG1)     // 98304

__global__ __launch_bounds__(128, 2) void gemm_hmma(
    const __half* __restrict__ Ah,
    const __half* __restrict__ Bs,
    const float* __restrict__ bias, float* __restrict__ Cf,
    __half* __restrict__ Ch,
    int N, int Ktot,
    long long sA, long long sB, long long sBias, long long sC)
{
    extern __shared__ __align__(128) char smem[];
    const int tid = threadIdx.x;
    const int wid = tid >> 5, lid = tid & 31;
    const int bz = blockIdx.z;
    const long long bm = (long long)blockIdx.y * 128;
    const long long bn = (long long)blockIdx.x * 128;

    const __half* gA0 = Ah + bz * sA + bm * Ktot;
    const __half* gB = Bs + bz * sB + bn * Ktot;
    const float* biasp = bias ? bias + bz * sBias : nullptr;

    const uint32_t sb = smem_u32(smem);
    const int wm = (wid & 1) * 64;
    const int wn = (wid >> 1) * 64;

    float acc[4][8][4];
    #pragma unroll
    for (int a = 0; a < 4; a++)
        #pragma unroll
        for (int b = 0; b < 8; b++)
            #pragma unroll
            for (int c = 0; c < 4; c++) acc[a][b][c] = 0.f;

    auto load_chunk = [&](int slot, int k0) {
        const uint32_t buf = sb + slot * STG1;
        #pragma unroll
        for (int it = 0; it < 8; it++) {
            int id = tid + it * 128;
            int r = id >> 3, c = id & 7;
            cp16(buf + r * 128 + (((c ^ r) & 7) << 4),
                 gA0 + (long long)r * Ktot + k0 + c * 8);
        }
        #pragma unroll
        for (int it = 0; it < 8; it++) {
            int id = tid + it * 128;
            int r = id >> 3, c = id & 7;
            cp16(buf + 16384 + r * 128 + ((c ^ (r & 7)) << 4),
                 gB + (long long)r * Ktot + k0 + c * 8);
        }
        cp_commit();
    };

    const int nc = Ktot >> 6;
    load_chunk(0, 0);
    load_chunk(1, 64);

    const int a_row = wm + (lid & 15);
    const int a_hi  = lid >> 4;
    const int b_row = wn + (lid & 7) + ((lid >> 4) & 1) * 8;
    const int b_hi  = (lid >> 3) & 1;

    uint32_t Af[2][4][4], Bf[2][4][4];
    auto ldsm_frags = [&](uint32_t buf, int kk, uint32_t A_[4][4], uint32_t B_[4][4]) {
        #pragma unroll
        for (int mb = 0; mb < 4; mb++) {
            int r = a_row + mb * 16;
            int c = kk * 2 + a_hi;
            ldsm_x4(A_[mb][0], A_[mb][1], A_[mb][2], A_[mb][3],
                    buf + r * 128 + ((c ^ (r & 7)) << 4));
        }
        #pragma unroll
        for (int nq = 0; nq < 4; nq++) {
            int r = b_row + nq * 16;
            int c = kk * 2 + b_hi;
            ldsm_x4(B_[nq][0], B_[nq][1], B_[nq][2], B_[nq][3],
                    buf + 16384 + r * 128 + ((c ^ (r & 7)) << 4));
        }
    };

    int slot = 0;
    for (int i = 0; i < nc; i++) {
        if (i + 1 < nc) cp_wait<1>(); else cp_wait<0>();
        __syncthreads();
        if (i + 2 < nc) {
            int ns = slot + 2; if (ns >= 3) ns -= 3;
            load_chunk(ns, (i + 2) << 6);
        }
        const uint32_t buf = sb + slot * STG1;
        ldsm_frags(buf, 0, Af[0], Bf[0]);
        #pragma unroll
        for (int kk = 0; kk < 4; kk++) {
            const int cur = kk & 1;
            if (kk < 3) ldsm_frags(buf, kk + 1, Af[cur ^ 1], Bf[cur ^ 1]);
            #pragma unroll
            for (int mb = 0; mb < 4; mb++)
                #pragma unroll
                for (int nq = 0; nq < 4; nq++)
                    #pragma unroll
                    for (int half = 0; half < 2; half++) {
                        float* c = acc[mb][nq * 2 + half];
                        mma_fp16(c[0], c[1], c[2], c[3],
                                 Af[cur][mb][0], Af[cur][mb][1], Af[cur][mb][2], Af[cur][mb][3],
                                 Bf[cur][nq][half * 2], Bf[cur][nq][half * 2 + 1]);
                    }
        }
        if (++slot == 3) slot = 0;
    }

    const int er = lid >> 2;
    const int ec = (lid & 3) * 2;
    #pragma unroll
    for (int mb = 0; mb < 4; mb++) {
        #pragma unroll
        for (int nb = 0; nb < 8; nb++) {
            const float* c = acc[mb][nb];
            long long col = bn + wn + nb * 8 + ec;
            float bx = 0.f, by = 0.f;
            if (biasp) { bx = biasp[col]; by = biasp[col + 1]; }
            long long r0 = bm + wm + mb * 16 + er;
            float v0 = c[0] + bx, v1 = c[1] + by;
            float v2 = c[2] + bx, v3 = c[3] + by;
            if (Cf) {
                float* Cb = Cf + bz * sC;
                *reinterpret_cast<float2*>(Cb + r0 * N + col) = make_float2(v0, v1);
                *reinterpret_cast<float2*>(Cb + (r0 + 8) * N + col) = make_float2(v2, v3);
            } else {
                __half2 s0 = { __float2half(v0), __float2half(v1) };
                __half2 s1 = { __float2half(v2), __float2half(v3) };
                __half* Hb = Ch + bz * sC;
                *reinterpret_cast<__half2*>(Hb + r0 * N + col) = s0;
                *reinterpret_cast<__half2*>(Hb + (r0 + 8) * N + col) = s1;
            }
        }
    }
}

// ---------------- FFT machinery (radix-4 Stockham, N=1024, 256 threads) ----------------
#define FPAD(i) ((i) + ((i) >> 5))

__device__ __forceinline__ void fft1024_stages(
    float* br0, float* bi0, float* br1, float* bi1,
    const float* twr, const float* twi, int tid, int inv)
{
    float *sr = br0, *si = bi0, *dr = br1, *di = bi1;
    const int Ls[5] = {256, 64, 16, 4, 1};
    const int Ms[5] = {1, 4, 16, 64, 256};
    #pragma unroll
    for (int st = 0; st < 5; st++) {
        const int l = Ls[st], m = Ms[st];
        int j = tid / m, k = tid - j * m;
        int ti = j * (256 / l);
        float w1r = twr[ti], w1i = twi[ti];
        float w2r = w1r * w1r - w1i * w1i, w2i = 2.f * w1r * w1i;
        float w3r = w2r * w1r - w2i * w1i, w3i = w2r * w1i + w2i * w1r;
        int i0 = k + m * j;
        float c0r = sr[FPAD(i0)],             c0i = si[FPAD(i0)];
        float c1r = sr[FPAD(i0 + m * l)],     c1i = si[FPAD(i0 + m * l)];
        float c2r = sr[FPAD(i0 + 2 * m * l)], c2i = si[FPAD(i0 + 2 * m * l)];
        float c3r = sr[FPAD(i0 + 3 * m * l)], c3i = si[FPAD(i0 + 3 * m * l)];
        float t0r = c0r + c2r, t0i = c0i + c2i;
        float t1r = c0r - c2r, t1i = c0i - c2i;
        float t2r = c1r + c3r, t2i = c1i + c3i;
        float t3r = c1r - c3r, t3i = c1i - c3i;
        float u0r = t0r + t2r, u0i = t0i + t2i;
        float u2r = t0r - t2r, u2i = t0i - t2i;
        float u1r, u1i, u3r, u3i;
        if (!inv) { u1r = t1r + t3i; u1i = t1i - t3r; u3r = t1r - t3i; u3i = t1i + t3r; }
        else      { u1r = t1r - t3i; u1i = t1i + t3r; u3r = t1r + t3i; u3i = t1i - t3r; }
        int o = k + 4 * m * j;
        dr[FPAD(o)]         = u0r;                    di[FPAD(o)]         = u0i;
        dr[FPAD(o + m)]     = w1r * u1r - w1i * u1i;  di[FPAD(o + m)]     = w1r * u1i + w1i * u1r;
        dr[FPAD(o + 2 * m)] = w2r * u2r - w2i * u2i;  di[FPAD(o + 2 * m)] = w2r * u2i + w2i * u2r;
        dr[FPAD(o + 3 * m)] = w3r * u3r - w3i * u3i;  di[FPAD(o + 3 * m)] = w3r * u3i + w3i * u3r;
        __syncthreads();
        float* t;
        t = sr; sr = dr; dr = t;
        t = si; si = di; di = t;
    }
}

// ---------------- fft_rows: forward FFT of Wk rows, Wv rows, bk, bv ----------------
// CTA c < Dd: Wk row c -> WkHat[c][Re|Im] fp32
// Dd <= c < 2Dd: Wv row e=c-Dd -> WvHatT[f][e] fp16 (rows 0-512 Re, 513-1025 Im)
// c == 2Dd: bk -> bhat[0..1025]; c == 2Dd+1: bv -> bhat[1026..2051]
__global__ __launch_bounds__(256) void fft_rows(
    const float* __restrict__ Wk, const float* __restrict__ Wv,
    const float* __restrict__ bk, const float* __restrict__ bv,
    float* __restrict__ WkHat, __half* __restrict__ WvHatT, float* __restrict__ bhat)
{
    __shared__ float Ar0[1056], Ai0[1056], Ar1[1056], Ai1[1056];
    __shared__ float twr[256], twi[256];
    const int tid = threadIdx.x;
    const int c = blockIdx.x;
    {
        float sv, cv;
        __sincosf(-6.28318530717958647692f * (float)tid / 1024.f, &sv, &cv);
        twr[tid] = cv; twi[tid] = sv;
    }
    const float* row;
    if (c < Dd) row = Wk + (long long)c * Dd;
    else if (c < 2 * Dd) row = Wv + (long long)(c - Dd) * Dd;
    else row = (c == 2 * Dd) ? bk : bv;

    #pragma unroll
    for (int q = 0; q < 4; q++) {
        int i = tid + 256 * q;
        Ar0[FPAD(i)] = row[i];
        Ai0[FPAD(i)] = 0.f;
    }
    __syncthreads();
    fft1024_stages(Ar0, Ai0, Ar1, Ai1, twr, twi, tid, 0);

    auto store = [&](int f, float Re, float Im) {
        if (c < Dd) {
            WkHat[(long long)c * 1026 + f] = Re;
            WkHat[(long long)c * 1026 + 513 + f] = Im;
        } else if (c < 2 * Dd) {
            int e = c - Dd;
            WvHatT[(long long)f * Dd + e] = __float2half(Re);
            WvHatT[(long long)(513 + f) * Dd + e] = __float2half(Im);
        } else {
            int o = (c - 2 * Dd) * 1026;
            bhat[o + f] = Re;
            bhat[o + 513 + f] = Im;
        }
    };
    #pragma unroll
    for (int h = 0; h < 2; h++) {
        int f = tid + h * 256;
        store(f, Ar1[FPAD(f)], Ai1[FPAD(f)]);
    }
    if (tid == 0) store(512, Ar1[FPAD(512)], Ai1[FPAD(512)]);
}

// ---------------- dot: S[b][f] = sum_e WkHat[e][f] * Y[b][e][f]  (complex) ----------------
#define ECHUNK 16
__global__ __launch_bounds__(256) void dot_S(
    const float* __restrict__ WkHat, const float* __restrict__ Y, float* __restrict__ S)
{
    const int b = blockIdx.y, tid = threadIdx.x;
    const int e0 = blockIdx.x * ECHUNK;
    const float* Yb = Y + (long long)b * Dd * 1152;
    float sr0 = 0, si0 = 0, sr1 = 0, si1 = 0, sr2 = 0, si2 = 0;
    for (int e = e0; e < e0 + ECHUNK; e++) {
        const float* w = WkHat + (long long)e * 1026;
        const float* y = Yb + (long long)e * 1152;
        {
            int f = tid;
            float Wr = w[f], Wi = w[513 + f], Yr = y[f], Yi = y[513 + f];
            sr0 += Wr * Yr - Wi * Yi;  si0 += Wr * Yi + Wi * Yr;
        }
        {
            int f = tid + 256;
            float Wr = w[f], Wi = w[513 + f], Yr = y[f], Yi = y[513 + f];
            sr1 += Wr * Yr - Wi * Yi;  si1 += Wr * Yi + Wi * Yr;
        }
        if (tid == 0) {
            int f = 512;
            float Wr = w[f], Wi = w[513 + f], Yr = y[f], Yi = y[513 + f];
            sr2 += Wr * Yr - Wi * Yi;  si2 += Wr * Yi + Wi * Yr;
        }
    }
    float* Sb = S + b * 513 * 2;
    atomicAdd(&Sb[tid * 2 + 0], sr0);        atomicAdd(&Sb[tid * 2 + 1], si0);
    atomicAdd(&Sb[(tid + 256) * 2 + 0], sr1); atomicAdd(&Sb[(tid + 256) * 2 + 1], si1);
    if (tid == 0) { atomicAdd(&Sb[512 * 2 + 0], sr2); atomicAdd(&Sb[512 * 2 + 1], si2); }
}

// ---------------- bias terms: S += bhv*Mk + bhk*Mv + T*bhk*bhv ----------------
__global__ __launch_bounds__(256) void bias_S(
    const float* __restrict__ mk, const float* __restrict__ mv,
    const float* __restrict__ bhat, float* __restrict__ S)
{
    __shared__ float Ar0[1056], Ai0[1056], Ar1[1056], Ai1[1056];
    __shared__ float twr[256], twi[256];
    const int b = blockIdx.x, tid = threadIdx.x;
    {
        float sv, cv;
        __sincosf(-6.28318530717958647692f * (float)tid / 1024.f, &sv, &cv);
        twr[tid] = cv; twi[tid] = sv;
    }
    #pragma unroll
    for (int q = 0; q < 4; q++) {
        int i = tid + 256 * q;
        Ar0[FPAD(i)] = mk[b * Dd + i];
        Ai0[FPAD(i)] = 0.f;
    }
    __syncthreads();
    fft1024_stages(Ar0, Ai0, Ar1, Ai1, twr, twi, tid, 0);
    float Mkr0 = Ar1[FPAD(tid)],       Mki0 = Ai1[FPAD(tid)];
    float Mkr1 = Ar1[FPAD(tid + 256)], Mki1 = Ai1[FPAD(tid + 256)];
    float Mkr2 = 0.f, Mki2 = 0.f;
    if (tid == 0) { Mkr2 = Ar1[FPAD(512)]; Mki2 = Ai1[FPAD(512)]; }
    __syncthreads();
    #pragma unroll
    for (int q = 0; q < 4; q++) {
        int i = tid + 256 * q;
        Ar0[FPAD(i)] = mv[b * Dd + i];
        Ai0[FPAD(i)] = 0.f;
    }
    __syncthreads();
    fft1024_stages(Ar0, Ai0, Ar1, Ai1, twr, twi, tid, 0);
    float Mvr0 = Ar1[FPAD(tid)],       Mvi0 = Ai1[FPAD(tid)];
    float Mvr1 = Ar1[FPAD(tid + 256)], Mvi1 = Ai1[FPAD(tid + 256)];
    float Mvr2 = 0.f, Mvi2 = 0.f;
    if (tid == 0) { Mvr2 = Ar1[FPAD(512)]; Mvi2 = Ai1[FPAD(512)]; }

    auto add = [&](int f, float Mkr, float Mki, float Mvr, float Mvi) {
        float bkr = bhat[f], bki = bhat[513 + f];
        float bvr = bhat[1026 + f], bvi = bhat[1026 + 513 + f];
        float Sr = bvr * Mkr - bvi * Mki + bkr * Mvr - bki * Mvi
                 + (float)Sq * (bkr * bvr - bki * bvi);
        float Si = bvr * Mki + bvi * Mkr + bkr * Mvi + bki * Mvr
                 + (float)Sq * (bkr * bvi + bki * bvr);
        S[b * 1026 + 2 * f]     += Sr;
        S[b * 1026 + 2 * f + 1] += Si;
    };
    add(tid, Mkr0, Mki0, Mvr0, Mvi0);
    add(tid + 256, Mkr1, Mki1, Mvr1, Mvi1);
    if (tid == 0) add(512, Mkr2, Mki2, Mvr2, Mvi2);
}

// ---------------- fft_w2 (unchanged): W2 rows + r via spectral unbind ----------------
__global__ __launch_bounds__(256) void fft_w2(
    const float* __restrict__ Wq, const float* __restrict__ bq,
    const float* __restrict__ Sacc,
    __half* __restrict__ W2tmp, float* __restrict__ r)
{
    __shared__ float Ar0[1056], Ai0[1056], Ar1[1056], Ai1[1056];
    __shared__ float twf_r[256], twf_i[256], twb_r[256], twb_i[256];
    const int tid = threadIdx.x;
    const int d = blockIdx.x;
    {
        float sv, cv;
        __sincosf(-6.28318530717958647692f * (float)tid / 1024.f, &sv, &cv);
        twf_r[tid] = cv; twf_i[tid] = sv;
        twb_r[tid] = cv; twb_i[tid] = -sv;
    }
    const float* wrow = (d < Dd) ? (Wq + (long long)d * Dd) : bq;
    #pragma unroll
    for (int q = 0; q < 4; q++) {
        int i = tid + 256 * q;
        Ar0[FPAD(i)] = wrow[i];
        Ai0[FPAD(i)] = 0.f;
    }
    __syncthreads();
    fft1024_stages(Ar0, Ai0, Ar1, Ai1, twf_r, twf_i, tid, 0);

    float Wr[4], Wi[4];
    #pragma unroll
    for (int q = 0; q < 4; q++) {
        int f = tid + 256 * q;
        Wr[q] = Ar1[FPAD(f)];
        Wi[q] = Ai1[FPAD(f)];
    }

    for (int b = 0; b < Bsz; b++) {
        const float* Sb = Sacc + b * 513 * 2;
        #pragma unroll
        for (int q = 0; q < 4; q++) {
            int f = tid + 256 * q;
            float Sr, Si;
            if (f <= 512) { Sr = Sb[f * 2]; Si = Sb[f * 2 + 1]; }
            else          { Sr = Sb[(1024 - f) * 2]; Si = -Sb[(1024 - f) * 2 + 1]; }
            Ar0[FPAD(f)] = Sr * Wr[q] + Si * Wi[q];
            Ai0[FPAD(f)] = Si * Wr[q] - Sr * Wi[q];
        }
        __syncthreads();
        fft1024_stages(Ar0, Ai0, Ar1, Ai1, twb_r, twb_i, tid, 1);
        if (d < Dd) {
            __half* dst = W2tmp + ((long long)b << 20) + ((long long)d << 10);
            #pragma unroll
            for (int q = 0; q < 4; q++) {
                int i = tid + 256 * q;
                dst[i] = __float2half(Ar1[FPAD(i)] * (1.f / 1024.f));
            }
        } else {
            float* dst = r + b * Dd;
            #pragma unroll
            for (int q = 0; q < 4; q++) {
                int i = tid + 256 * q;
                dst[i] = Ar1[FPAD(i)] * (1.f / 1024.f);
            }
        }
    }
}

// ---------------- prep / small kernels ----------------
__global__ void zero_S(float* p, int n)
{
    int i = blockIdx.x * 256 + threadIdx.x;
    if (i < n) p[i] = 0.f;
}

__global__ void zero_wvpad(__half* p)
{
    int i = blockIdx.x * 256 + threadIdx.x;      // pad rows 1026..1151: 126*1024/2 half2
    if (i < 126 * Dd / 2)
        reinterpret_cast<__half2*>(p + 1026 * Dd)[i] = __half2{__float2half(0.f), __float2half(0.f)};
}

__global__ void conv_f16v(const float4* __restrict__ x, __half2* __restrict__ h, long long n4)
{
    long long i = (long long)blockIdx.x * blockDim.x + threadIdx.x;
    if (i < n4) {
        float4 v = x[i];
        h[i * 2 + 0] = __half2{__float2half(v.x), __float2half(v.y)};
        h[i * 2 + 1] = __half2{__float2half(v.z), __float2half(v.w)};
    }
}

__global__ void transpose_f16(const __half* __restrict__ s, __half* __restrict__ d,
                              int R, int C, long long sIn, long long sOut)
{
    __shared__ __half t[64][65];
    int b = blockIdx.z;
    s += (long long)b * sIn; d += (long long)b * sOut;
    int c0 = blockIdx.x * 64, r0 = blockIdx.y * 64;
    int tid = threadIdx.x;
    #pragma unroll
    for (int it = 0; it < 8; it++) {
        int id = tid + it * 256;
        int row = id >> 5, cp = (id & 31) * 2;
        __half2 v = *reinterpret_cast<const __half2*>(s + (long long)(r0 + row) * C + c0 + cp);
        t[row][cp] = v.x; t[row][cp + 1] = v.y;
    }
    __syncthreads();
    #pragma unroll
    for (int it = 0; it < 8; it++) {
        int id = tid + it * 256;
        int cc = id >> 5, rp = (id & 31) * 2;
        __half2 v = { t[rp][cc], t[rp + 1][cc] };
        *reinterpret_cast<__half2*>(d + (long long)(c0 + cc) * R + r0 + rp) = v;
    }
}

// m[b][e] = sum_t xTh[b][e][t]
__global__ __launch_bounds__(256) void colsum(const __half* __restrict__ xTh,
                                              float* __restrict__ m)
{
    __shared__ float red[8];
    const int b = blockIdx.y, e = blockIdx.x, tid = threadIdx.x;
    const __half* row = xTh + (long long)b * Sq * Dd + (long long)e * Sq;
    float a = 0.f;
    #pragma unroll
    for (int k = 0; k < 16; k++) a += __half2float(row[tid + k * 256]);
    #pragma unroll
    for (int o = 16; o; o >>= 1) a += __shfl_xor_sync(0xffffffffu, a, o);
    if ((tid & 31) == 0) red[tid >> 5] = a;
    __syncthreads();
    if (tid < 8) {
        float v = red[tid];
        #pragma unroll
        for (int o = 4; o; o >>= 1) v += __shfl_xor_sync(0xffu, v, o);
        if (tid == 0) m[b * Dd + e] = v;
    }
}

// mk[b] = m[b] @ Wk ; mv[b] = m[b] @ Wv
__global__ void gemv_mw(const float* __restrict__ Wk, const float* __restrict__ Wv,
                        const float* __restrict__ m,
                        float* __restrict__ mk, float* __restrict__ mv)
{
    int d = blockIdx.x * 256 + threadIdx.x;
    const float* W = blockIdx.y ? Wv : Wk;
    float* o = blockIdx.y ? mv : mk;
    float a0 = 0, a1 = 0, a2 = 0, a3 = 0;
    for (int e = 0; e < Dd; e++) {
        float w = W[(long long)e * Dd + d];
        a0 += m[e] * w;
        a1 += m[Dd + e] * w;
        a2 += m[2 * Dd + e] * w;
        a3 += m[3 * Dd + e] * w;
    }
    o[d] = a0; o[Dd + d] = a1; o[2 * Dd + d] = a2; o[3 * Dd + d] = a3;
}

// ---------------- launcher ----------------
extern "C" void kernel_launch(void* const* d_in, const int* in_sizes, int n_in,
                              void* d_out, int out_size)
{
    const float* x  = (const float*)d_in[0];
    const float* Wq = (const float*)d_in[1];
    const float* bq = (const float*)d_in[2];
    const float* Wk = (const float*)d_in[3];
    const float* bk = (const float*)d_in[4];
    const float* Wv = (const float*)d_in[5];
    const float* bv = (const float*)d_in[6];
    float* out = (float*)d_out;

    __half *xh, *xTh, *Gh, *WvHatT, *W2tmp, *W2Ts;
    float *WkHat, *bhat, *Y, *m, *mk, *mv, *S, *r;
    cudaGetSymbolAddress((void**)&xh, g_xh);
    cudaGetSymbolAddress((void**)&xTh, g_xTh);
    cudaGetSymbolAddress((void**)&Gh, g_Gh);
    cudaGetSymbolAddress((void**)&WkHat, g_WkHat);
    cudaGetSymbolAddress((void**)&WvHatT, g_WvHatT);
    cudaGetSymbolAddress((void**)&bhat, g_bhat);
    cudaGetSymbolAddress((void**)&Y, g_Y);
    cudaGetSymbolAddress((void**)&m, g_m);
    cudaGetSymbolAddress((void**)&mk, g_mk);
    cudaGetSymbolAddress((void**)&mv, g_mv);
    cudaGetSymbolAddress((void**)&S, g_S);
    cudaGetSymbolAddress((void**)&r, g_r);
    cudaGetSymbolAddress((void**)&W2tmp, g_W2tmp);
    cudaGetSymbolAddress((void**)&W2Ts, g_W2Ts);

    cudaFuncSetAttribute(gemm_hmma, cudaFuncAttributeMaxDynamicSharedMemorySize, DSMEM1);

    const long long nBS = (long long)BS * Dd;       // 16M
    const long long dd  = (long long)Dd * Dd;       // 1M
    const long long sd  = (long long)Sq * Dd;       // 4M

    // 0) prep: x -> fp16; x^T per batch; row-FFTs of Wk/Wv/bk/bv; zeros
    conv_f16v<<<(unsigned)(nBS / 4 / 256), 256>>>((const float4*)x, (__half2*)xh, nBS / 4);
    transpose_f16<<<dim3(Dd / 64, Sq / 64, Bsz), 256>>>(xh, xTh, Sq, Dd, sd, sd);
    fft_rows<<<2 * Dd + 2, 256>>>(Wk, Wv, bk, bv, WkHat, WvHatT, bhat);
    zero_wvpad<<<252, 256>>>(WvHatT);
    zero_S<<<(Bsz * 513 * 2 + 255) / 256, 256>>>(S, Bsz * 513 * 2);

    // bias path: m = col-sums of x; mk = m@Wk, mv = m@Wv
    colsum<<<dim3(Dd, Bsz), 256>>>(xTh, m);
    gemv_mw<<<dim3(Dd / 256, 2), 256>>>(Wk, Wv, m, mk, mv);

    // 1) Gram: G_b = xT_b @ xT_b^T  (M=N=1024, K=4096) -> fp16
    gemm_hmma<<<dim3(Dd / 128, Dd / 128, Bsz), 128, DSMEM1>>>(
        xTh, xTh, nullptr, nullptr, Gh, Dd, Sq, sd, sd, 0, dd);

    // 2) Y_b = G_b @ WvHat  (N=1152 = 513 Re + 513 Im + pad) -> fp32
    gemm_hmma<<<dim3(1152 / 128, Dd / 128, Bsz), 128, DSMEM1>>>(
        Gh, WvHatT, nullptr, Y, nullptr, 1152, Dd, dd, 0, 0, (long long)Dd * 1152);

    // 3) S[b][f] = sum_e WkHat[e][f] * Y[b][e][f]  (+ bias spectrum terms)
    dot_S<<<dim3(Dd / ECHUNK, Bsz), 256>>>(WkHat, Y, S);
    bias_S<<<Bsz, 256>>>(mk, mv, bhat, S);

    // 4) W2 rows (d<Dd) + r (d==Dd) via spectral unbind; transpose to [n][d]
    fft_w2<<<Dd + 1, 256>>>(Wq, bq, S, W2tmp, r);
    transpose_f16<<<dim3(Dd / 64, Dd / 64, Bsz), 256>>>(W2tmp, W2Ts, Dd, Dd, dd, dd);

    // 5) out_b = x_b @ W2_b + r_b  (fp32 out)
    gemm_hmma<<<dim3(Dd / 128, Sq / 128, Bsz), 128, DSMEM1>>>(
        xh, W2Ts, r, out, nullptr, Dd, Dd, sd, dd, Dd, sd);
}

// round 15
// speedup vs baseline: 1.2417x; 1.2417x over previous
#include <cuda_runtime.h>
#include <cuda_fp16.h>
#include <stdint.h>

#define Bsz 4
#define Sq  4096
#define Dd  1024
#define BS  (Bsz * Sq)   // 16384

// ---------------- scratch (device globals — allocation is forbidden) ----------------
__device__ __align__(256) __half g_xh[(long long)BS * Dd];          // x fp16 [t][d]
__device__ __align__(256) __half g_xTh[(long long)BS * Dd];         // x^T fp16 [b][d][t]
__device__ __align__(256) __half g_Gh[(long long)Bsz * Dd * Dd];    // Gram fp16 [b][e][e']
__device__ __align__(256) float  g_WkHat[(long long)Dd * 1026];     // [e][Re 513 | Im 513]
__device__ __align__(256) __half g_WvHatT[(long long)1152 * Dd];    // [f-comp][e] rows 0-512 Re, 513-1025 Im
__device__ __align__(256) float  g_bhat[2 * 1026];                  // bk-hat, bv-hat
__device__ __align__(256) float  g_Y[(long long)Bsz * Dd * 1152];   // G @ WvHat (fp32)
__device__ __align__(256) float  g_m[Bsz * Dd];
__device__ __align__(256) float  g_mk[Bsz * Dd];
__device__ __align__(256) float  g_mv[Bsz * Dd];
__device__ __align__(256) float  g_S[Bsz * 513 * 2];
__device__ __align__(256) float  g_r[Bsz * Dd];
__device__ __align__(256) __half g_W2tmp[(long long)Bsz * Dd * Dd]; // [b][d][n]
__device__ __align__(256) __half g_W2Ts[(long long)Bsz * Dd * Dd];  // [b][n][d]

// ---------------- PTX helpers ----------------
__device__ __forceinline__ uint32_t smem_u32(const void* p) {
    uint32_t a;
    asm("{ .reg .u64 t; cvta.to.shared.u64 t, %1; cvt.u32.u64 %0, t; }" : "=r"(a) : "l"(p));
    return a;
}
__device__ __forceinline__ void cp16(uint32_t dst, const void* src) {
    asm volatile("cp.async.cg.shared.global [%0], [%1], 16;" :: "r"(dst), "l"(src));
}
__device__ __forceinline__ void cp_commit() { asm volatile("cp.async.commit_group;" ::: "memory"); }
template<int N> __device__ __forceinline__ void cp_wait() {
    asm volatile("cp.async.wait_group %0;" :: "n"(N) : "memory");
}

__device__ __forceinline__ void ldsm_x4(uint32_t& r0, uint32_t& r1, uint32_t& r2, uint32_t& r3,
                                        uint32_t addr) {
    asm volatile("ldmatrix.sync.aligned.m8n8.x4.shared.b16 {%0,%1,%2,%3}, [%4];"
                 : "=r"(r0), "=r"(r1), "=r"(r2), "=r"(r3) : "r"(addr));
}
__device__ __forceinline__ void mma_fp16(float& c0, float& c1, float& c2, float& c3,
                                         uint32_t a0, uint32_t a1, uint32_t a2, uint32_t a3,
                                         uint32_t b0, uint32_t b1) {
    asm volatile(
        "mma.sync.aligned.m16n8k16.row.col.f32.f16.f16.f32 "
        "{%0,%1,%2,%3}, {%4,%5,%6,%7}, {%8,%9}, {%0,%1,%2,%3};"
        : "+f"(c0), "+f"(c1), "+f"(c2), "+f"(c3)
        : "r"(a0), "r"(a1), "r"(a2), "r"(a3), "r"(b0), "r"(b1));
}

// ---------------- fp16 HMMA GEMM (frozen since R12) ----------------
#define STG1 32768
#define DSMEM1 (3 * STG1)     // 98304

__global__ __launch_bounds__(128, 2) void gemm_hmma(
    const __half* __restrict__ Ah,
    const __half* __restrict__ Bs,
    const float* __restrict__ bias, float* __restrict__ Cf,
    __half* __restrict__ Ch,
    int N, int Ktot,
    long long sA, long long sB, long long sBias, long long sC)
{
    extern __shared__ __align__(128) char smem[];
    const int tid = threadIdx.x;
    const int wid = tid >> 5, lid = tid & 31;
    const int bz = blockIdx.z;
    const long long bm = (long long)blockIdx.y * 128;
    const long long bn = (long long)blockIdx.x * 128;

    const __half* gA0 = Ah + bz * sA + bm * Ktot;
    const __half* gB = Bs + bz * sB + bn * Ktot;
    const float* biasp = bias ? bias + bz * sBias : nullptr;

    const uint32_t sb = smem_u32(smem);
    const int wm = (wid & 1) * 64;
    const int wn = (wid >> 1) * 64;

    float acc[4][8][4];
    #pragma unroll
    for (int a = 0; a < 4; a++)
        #pragma unroll
        for (int b = 0; b < 8; b++)
            #pragma unroll
            for (int c = 0; c < 4; c++) acc[a][b][c] = 0.f;

    auto load_chunk = [&](int slot, int k0) {
        const uint32_t buf = sb + slot * STG1;
        #pragma unroll
        for (int it = 0; it < 8; it++) {
            int id = tid + it * 128;
            int r = id >> 3, c = id & 7;
            cp16(buf + r * 128 + (((c ^ r) & 7) << 4),
                 gA0 + (long long)r * Ktot + k0 + c * 8);
        }
        #pragma unroll
        for (int it = 0; it < 8; it++) {
            int id = tid + it * 128;
            int r = id >> 3, c = id & 7;
            cp16(buf + 16384 + r * 128 + ((c ^ (r & 7)) << 4),
                 gB + (long long)r * Ktot + k0 + c * 8);
        }
        cp_commit();
    };

    const int nc = Ktot >> 6;
    load_chunk(0, 0);
    load_chunk(1, 64);

    const int a_row = wm + (lid & 15);
    const int a_hi  = lid >> 4;
    const int b_row = wn + (lid & 7) + ((lid >> 4) & 1) * 8;
    const int b_hi  = (lid >> 3) & 1;

    uint32_t Af[2][4][4], Bf[2][4][4];
    auto ldsm_frags = [&](uint32_t buf, int kk, uint32_t A_[4][4], uint32_t B_[4][4]) {
        #pragma unroll
        for (int mb = 0; mb < 4; mb++) {
            int r = a_row + mb * 16;
            int c = kk * 2 + a_hi;
            ldsm_x4(A_[mb][0], A_[mb][1], A_[mb][2], A_[mb][3],
                    buf + r * 128 + ((c ^ (r & 7)) << 4));
        }
        #pragma unroll
        for (int nq = 0; nq < 4; nq++) {
            int r = b_row + nq * 16;
            int c = kk * 2 + b_hi;
            ldsm_x4(B_[nq][0], B_[nq][1], B_[nq][2], B_[nq][3],
                    buf + 16384 + r * 128 + ((c ^ (r & 7)) << 4));
        }
    };

    int slot = 0;
    for (int i = 0; i < nc; i++) {
        if (i + 1 < nc) cp_wait<1>(); else cp_wait<0>();
        __syncthreads();
        if (i + 2 < nc) {
            int ns = slot + 2; if (ns >= 3) ns -= 3;
            load_chunk(ns, (i + 2) << 6);
        }
        const uint32_t buf = sb + slot * STG1;
        ldsm_frags(buf, 0, Af[0], Bf[0]);
        #pragma unroll
        for (int kk = 0; kk < 4; kk++) {
            const int cur = kk & 1;
            if (kk < 3) ldsm_frags(buf, kk + 1, Af[cur ^ 1], Bf[cur ^ 1]);
            #pragma unroll
            for (int mb = 0; mb < 4; mb++)
                #pragma unroll
                for (int nq = 0; nq < 4; nq++)
                    #pragma unroll
                    for (int half = 0; half < 2; half++) {
                        float* c = acc[mb][nq * 2 + half];
                        mma_fp16(c[0], c[1], c[2], c[3],
                                 Af[cur][mb][0], Af[cur][mb][1], Af[cur][mb][2], Af[cur][mb][3],
                                 Bf[cur][nq][half * 2], Bf[cur][nq][half * 2 + 1]);
                    }
        }
        if (++slot == 3) slot = 0;
    }

    const int er = lid >> 2;
    const int ec = (lid & 3) * 2;
    #pragma unroll
    for (int mb = 0; mb < 4; mb++) {
        #pragma unroll
        for (int nb = 0; nb < 8; nb++) {
            const float* c = acc[mb][nb];
            long long col = bn + wn + nb * 8 + ec;
            float bx = 0.f, by = 0.f;
            if (biasp) { bx = biasp[col]; by = biasp[col + 1]; }
            long long r0 = bm + wm + mb * 16 + er;
            float v0 = c[0] + bx, v1 = c[1] + by;
            float v2 = c[2] + bx, v3 = c[3] + by;
            if (Cf) {
                float* Cb = Cf + bz * sC;
                *reinterpret_cast<float2*>(Cb + r0 * N + col) = make_float2(v0, v1);
                *reinterpret_cast<float2*>(Cb + (r0 + 8) * N + col) = make_float2(v2, v3);
            } else {
                __half2 s0 = { __float2half(v0), __float2half(v1) };
                __half2 s1 = { __float2half(v2), __float2half(v3) };
                __half* Hb = Ch + bz * sC;
                *reinterpret_cast<__half2*>(Hb + r0 * N + col) = s0;
                *reinterpret_cast<__half2*>(Hb + (r0 + 8) * N + col) = s1;
            }
        }
    }
}

// ---------------- FFT machinery (radix-4 Stockham, N=1024, 256 threads) ----------------
#define FPAD(i) ((i) + ((i) >> 5))

__device__ __forceinline__ void fft1024_stages(
    float* br0, float* bi0, float* br1, float* bi1,
    const float* twr, const float* twi, int tid, int inv)
{
    float *sr = br0, *si = bi0, *dr = br1, *di = bi1;
    const int Ls[5] = {256, 64, 16, 4, 1};
    const int Ms[5] = {1, 4, 16, 64, 256};
    #pragma unroll
    for (int st = 0; st < 5; st++) {
        const int l = Ls[st], m = Ms[st];
        int j = tid / m, k = tid - j * m;
        int ti = j * (256 / l);
        float w1r = twr[ti], w1i = twi[ti];
        float w2r = w1r * w1r - w1i * w1i, w2i = 2.f * w1r * w1i;
        float w3r = w2r * w1r - w2i * w1i, w3i = w2r * w1i + w2i * w1r;
        int i0 = k + m * j;
        float c0r = sr[FPAD(i0)],             c0i = si[FPAD(i0)];
        float c1r = sr[FPAD(i0 + m * l)],     c1i = si[FPAD(i0 + m * l)];
        float c2r = sr[FPAD(i0 + 2 * m * l)], c2i = si[FPAD(i0 + 2 * m * l)];
        float c3r = sr[FPAD(i0 + 3 * m * l)], c3i = si[FPAD(i0 + 3 * m * l)];
        float t0r = c0r + c2r, t0i = c0i + c2i;
        float t1r = c0r - c2r, t1i = c0i - c2i;
        float t2r = c1r + c3r, t2i = c1i + c3i;
        float t3r = c1r - c3r, t3i = c1i - c3i;
        float u0r = t0r + t2r, u0i = t0i + t2i;
        float u2r = t0r - t2r, u2i = t0i - t2i;
        float u1r, u1i, u3r, u3i;
        if (!inv) { u1r = t1r + t3i; u1i = t1i - t3r; u3r = t1r - t3i; u3i = t1i + t3r; }
        else      { u1r = t1r - t3i; u1i = t1i + t3r; u3r = t1r + t3i; u3i = t1i - t3r; }
        int o = k + 4 * m * j;
        dr[FPAD(o)]         = u0r;                    di[FPAD(o)]         = u0i;
        dr[FPAD(o + m)]     = w1r * u1r - w1i * u1i;  di[FPAD(o + m)]     = w1r * u1i + w1i * u1r;
        dr[FPAD(o + 2 * m)] = w2r * u2r - w2i * u2i;  di[FPAD(o + 2 * m)] = w2r * u2i + w2i * u2r;
        dr[FPAD(o + 3 * m)] = w3r * u3r - w3i * u3i;  di[FPAD(o + 3 * m)] = w3r * u3i + w3i * u3r;
        __syncthreads();
        float* t;
        t = sr; sr = dr; dr = t;
        t = si; si = di; di = t;
    }
}

// ---------------- fft_rows: FFT of Wk rows, Wv rows, bk, bv (+ WvHatT pad zero) ----------------
__global__ __launch_bounds__(256) void fft_rows(
    const float* __restrict__ Wk, const float* __restrict__ Wv,
    const float* __restrict__ bk, const float* __restrict__ bv,
    float* __restrict__ WkHat, __half* __restrict__ WvHatT, float* __restrict__ bhat)
{
    __shared__ float Ar0[1056], Ai0[1056], Ar1[1056], Ai1[1056];
    __shared__ float twr[256], twi[256];
    const int tid = threadIdx.x;
    const int c = blockIdx.x;
    if (c < 126) {   // zero pad rows 1026..1151 of WvHatT
        __half2 z = { __float2half(0.f), __float2half(0.f) };
        __half2* p = reinterpret_cast<__half2*>(WvHatT + (long long)(1026 + c) * Dd);
        p[tid] = z;
        p[tid + 256] = z;
    }
    {
        float sv, cv;
        __sincosf(-6.28318530717958647692f * (float)tid / 1024.f, &sv, &cv);
        twr[tid] = cv; twi[tid] = sv;
    }
    const float* row;
    if (c < Dd) row = Wk + (long long)c * Dd;
    else if (c < 2 * Dd) row = Wv + (long long)(c - Dd) * Dd;
    else row = (c == 2 * Dd) ? bk : bv;

    #pragma unroll
    for (int q = 0; q < 4; q++) {
        int i = tid + 256 * q;
        Ar0[FPAD(i)] = row[i];
        Ai0[FPAD(i)] = 0.f;
    }
    __syncthreads();
    fft1024_stages(Ar0, Ai0, Ar1, Ai1, twr, twi, tid, 0);

    auto store = [&](int f, float Re, float Im) {
        if (c < Dd) {
            WkHat[(long long)c * 1026 + f] = Re;
            WkHat[(long long)c * 1026 + 513 + f] = Im;
        } else if (c < 2 * Dd) {
            int e = c - Dd;
            WvHatT[(long long)f * Dd + e] = __float2half(Re);
            WvHatT[(long long)(513 + f) * Dd + e] = __float2half(Im);
        } else {
            int o = (c - 2 * Dd) * 1026;
            bhat[o + f] = Re;
            bhat[o + 513 + f] = Im;
        }
    };
    #pragma unroll
    for (int h = 0; h < 2; h++) {
        int f = tid + h * 256;
        store(f, Ar1[FPAD(f)], Ai1[FPAD(f)]);
    }
    if (tid == 0) store(512, Ar1[FPAD(512)], Ai1[FPAD(512)]);
}

// ---------------- dot: S[b][f] = sum_e WkHat[e][f] * Y[b][e][f]  (complex) ----------------
#define ECHUNK 16
__global__ __launch_bounds__(256) void dot_S(
    const float* __restrict__ WkHat, const float* __restrict__ Y, float* __restrict__ S)
{
    const int b = blockIdx.y, tid = threadIdx.x;
    const int e0 = blockIdx.x * ECHUNK;
    const float* Yb = Y + (long long)b * Dd * 1152;
    float sr0 = 0, si0 = 0, sr1 = 0, si1 = 0, sr2 = 0, si2 = 0;
    for (int e = e0; e < e0 + ECHUNK; e++) {
        const float* w = WkHat + (long long)e * 1026;
        const float* y = Yb + (long long)e * 1152;
        {
            int f = tid;
            float Wr = w[f], Wi = w[513 + f], Yr = y[f], Yi = y[513 + f];
            sr0 += Wr * Yr - Wi * Yi;  si0 += Wr * Yi + Wi * Yr;
        }
        {
            int f = tid + 256;
            float Wr = w[f], Wi = w[513 + f], Yr = y[f], Yi = y[513 + f];
            sr1 += Wr * Yr - Wi * Yi;  si1 += Wr * Yi + Wi * Yr;
        }
        if (tid == 0) {
            int f = 512;
            float Wr = w[f], Wi = w[513 + f], Yr = y[f], Yi = y[513 + f];
            sr2 += Wr * Yr - Wi * Yi;  si2 += Wr * Yi + Wi * Yr;
        }
    }
    float* Sb = S + b * 513 * 2;
    atomicAdd(&Sb[tid * 2 + 0], sr0);        atomicAdd(&Sb[tid * 2 + 1], si0);
    atomicAdd(&Sb[(tid + 256) * 2 + 0], sr1); atomicAdd(&Sb[(tid + 256) * 2 + 1], si1);
    if (tid == 0) { atomicAdd(&Sb[512 * 2 + 0], sr2); atomicAdd(&Sb[512 * 2 + 1], si2); }
}

// ---------------- bias terms: S += bhv*Mk + bhk*Mv + T*bhk*bhv ----------------
__global__ __launch_bounds__(256) void bias_S(
    const float* __restrict__ mk, const float* __restrict__ mv,
    const float* __restrict__ bhat, float* __restrict__ S)
{
    __shared__ float Ar0[1056], Ai0[1056], Ar1[1056], Ai1[1056];
    __shared__ float twr[256], twi[256];
    const int b = blockIdx.x, tid = threadIdx.x;
    {
        float sv, cv;
        __sincosf(-6.28318530717958647692f * (float)tid / 1024.f, &sv, &cv);
        twr[tid] = cv; twi[tid] = sv;
    }
    #pragma unroll
    for (int q = 0; q < 4; q++) {
        int i = tid + 256 * q;
        Ar0[FPAD(i)] = mk[b * Dd + i];
        Ai0[FPAD(i)] = 0.f;
    }
    __syncthreads();
    fft1024_stages(Ar0, Ai0, Ar1, Ai1, twr, twi, tid, 0);
    float Mkr0 = Ar1[FPAD(tid)],       Mki0 = Ai1[FPAD(tid)];
    float Mkr1 = Ar1[FPAD(tid + 256)], Mki1 = Ai1[FPAD(tid + 256)];
    float Mkr2 = 0.f, Mki2 = 0.f;
    if (tid == 0) { Mkr2 = Ar1[FPAD(512)]; Mki2 = Ai1[FPAD(512)]; }
    __syncthreads();
    #pragma unroll
    for (int q = 0; q < 4; q++) {
        int i = tid + 256 * q;
        Ar0[FPAD(i)] = mv[b * Dd + i];
        Ai0[FPAD(i)] = 0.f;
    }
    __syncthreads();
    fft1024_stages(Ar0, Ai0, Ar1, Ai1, twr, twi, tid, 0);
    float Mvr0 = Ar1[FPAD(tid)],       Mvi0 = Ai1[FPAD(tid)];
    float Mvr1 = Ar1[FPAD(tid + 256)], Mvi1 = Ai1[FPAD(tid + 256)];
    float Mvr2 = 0.f, Mvi2 = 0.f;
    if (tid == 0) { Mvr2 = Ar1[FPAD(512)]; Mvi2 = Ai1[FPAD(512)]; }

    auto add = [&](int f, float Mkr, float Mki, float Mvr, float Mvi) {
        float bkr = bhat[f], bki = bhat[513 + f];
        float bvr = bhat[1026 + f], bvi = bhat[1026 + 513 + f];
        float Sr = bvr * Mkr - bvi * Mki + bkr * Mvr - bki * Mvi
                 + (float)Sq * (bkr * bvr - bki * bvi);
        float Si = bvr * Mki + bvi * Mkr + bkr * Mvi + bki * Mvr
                 + (float)Sq * (bkr * bvi + bki * bvr);
        S[b * 1026 + 2 * f]     += Sr;
        S[b * 1026 + 2 * f + 1] += Si;
    };
    add(tid, Mkr0, Mki0, Mvr0, Mvi0);
    add(tid + 256, Mkr1, Mki1, Mvr1, Mvi1);
    if (tid == 0) add(512, Mkr2, Mki2, Mvr2, Mvi2);
}

// ---------------- fft_w2: W2 rows (d<Dd) + r (d==Dd) via spectral unbind ----------------
__global__ __launch_bounds__(256) void fft_w2(
    const float* __restrict__ Wq, const float* __restrict__ bq,
    const float* __restrict__ Sacc,
    __half* __restrict__ W2tmp, float* __restrict__ r)
{
    __shared__ float Ar0[1056], Ai0[1056], Ar1[1056], Ai1[1056];
    __shared__ float twf_r[256], twf_i[256], twb_r[256], twb_i[256];
    const int tid = threadIdx.x;
    const int d = blockIdx.x;
    {
        float sv, cv;
        __sincosf(-6.28318530717958647692f * (float)tid / 1024.f, &sv, &cv);
        twf_r[tid] = cv; twf_i[tid] = sv;
        twb_r[tid] = cv; twb_i[tid] = -sv;
    }
    const float* wrow = (d < Dd) ? (Wq + (long long)d * Dd) : bq;
    #pragma unroll
    for (int q = 0; q < 4; q++) {
        int i = tid + 256 * q;
        Ar0[FPAD(i)] = wrow[i];
        Ai0[FPAD(i)] = 0.f;
    }
    __syncthreads();
    fft1024_stages(Ar0, Ai0, Ar1, Ai1, twf_r, twf_i, tid, 0);

    float Wr[4], Wi[4];
    #pragma unroll
    for (int q = 0; q < 4; q++) {
        int f = tid + 256 * q;
        Wr[q] = Ar1[FPAD(f)];
        Wi[q] = Ai1[FPAD(f)];
    }

    for (int b = 0; b < Bsz; b++) {
        const float* Sb = Sacc + b * 513 * 2;
        #pragma unroll
        for (int q = 0; q < 4; q++) {
            int f = tid + 256 * q;
            float Sr, Si;
            if (f <= 512) { Sr = Sb[f * 2]; Si = Sb[f * 2 + 1]; }
            else          { Sr = Sb[(1024 - f) * 2]; Si = -Sb[(1024 - f) * 2 + 1]; }
            Ar0[FPAD(f)] = Sr * Wr[q] + Si * Wi[q];
            Ai0[FPAD(f)] = Si * Wr[q] - Sr * Wi[q];
        }
        __syncthreads();
        fft1024_stages(Ar0, Ai0, Ar1, Ai1, twb_r, twb_i, tid, 1);
        if (d < Dd) {
            __half* dst = W2tmp + ((long long)b << 20) + ((long long)d << 10);
            #pragma unroll
            for (int q = 0; q < 4; q++) {
                int i = tid + 256 * q;
                dst[i] = __float2half(Ar1[FPAD(i)] * (1.f / 1024.f));
            }
        } else {
            float* dst = r + b * Dd;
            #pragma unroll
            for (int q = 0; q < 4; q++) {
                int i = tid + 256 * q;
                dst[i] = Ar1[FPAD(i)] * (1.f / 1024.f);
            }
        }
    }
}

// ---------------- fused x prep: xh (same layout) + xTh (transposed) + colsum m ----------------
__global__ __launch_bounds__(256) void prep_x(
    const float* __restrict__ x, __half* __restrict__ xh, __half* __restrict__ xTh,
    float* __restrict__ m)
{
    __shared__ __half th[64][65];
    const int b = blockIdx.z;
    const int t0 = blockIdx.y * 64, d0 = blockIdx.x * 64;
    const int tid = threadIdx.x;
    const long long xbase = ((long long)b * Sq + t0) * Dd + d0;
    const int c = tid & 63, rq = tid >> 6;
    float csum = 0.f;
    #pragma unroll
    for (int k = 0; k < 16; k++) {
        int rr = rq + k * 4;
        float v = x[xbase + (long long)rr * Dd + c];
        __half h = __float2half(v);
        xh[xbase + (long long)rr * Dd + c] = h;
        th[rr][c] = h;
        csum += v;
    }
    atomicAdd(&m[b * Dd + d0 + c], csum);
    __syncthreads();
    const long long obase = ((long long)b * Dd + d0) * Sq + t0;
    #pragma unroll
    for (int it = 0; it < 8; it++) {
        int id = tid + it * 256;
        int cc = id >> 5, rp = (id & 31) * 2;
        __half2 v = { th[rp][cc], th[rp + 1][cc] };
        *reinterpret_cast<__half2*>(xTh + obase + (long long)cc * Sq + rp) = v;
    }
}

// ---------------- misc small kernels ----------------
__global__ void zero_all(float* S, float* m, float* mk, float* mv)
{
    int i = blockIdx.x * 256 + threadIdx.x;
    if (i < Bsz * 513 * 2) S[i] = 0.f;
    if (i < Bsz * Dd) { m[i] = 0.f; mk[i] = 0.f; mv[i] = 0.f; }
}

// mk = m@Wk ; mv = m@Wv (e-chunked with atomics)
__global__ void gemv_mw(const float* __restrict__ Wk, const float* __restrict__ Wv,
                        const float* __restrict__ m,
                        float* __restrict__ mk, float* __restrict__ mv)
{
    int d = blockIdx.x * 256 + threadIdx.x;
    int e0 = blockIdx.z * 256;
    const float* W = blockIdx.y ? Wv : Wk;
    float* o = blockIdx.y ? mv : mk;
    float a0 = 0, a1 = 0, a2 = 0, a3 = 0;
    for (int e = e0; e < e0 + 256; e++) {
        float w = W[(long long)e * Dd + d];
        a0 += m[e] * w;
        a1 += m[Dd + e] * w;
        a2 += m[2 * Dd + e] * w;
        a3 += m[3 * Dd + e] * w;
    }
    atomicAdd(&o[d], a0);
    atomicAdd(&o[Dd + d], a1);
    atomicAdd(&o[2 * Dd + d], a2);
    atomicAdd(&o[3 * Dd + d], a3);
}

__global__ void transpose_f16(const __half* __restrict__ s, __half* __restrict__ d,
                              int R, int C, long long sIn, long long sOut)
{
    __shared__ __half t[64][65];
    int b = blockIdx.z;
    s += (long long)b * sIn; d += (long long)b * sOut;
    int c0 = blockIdx.x * 64, r0 = blockIdx.y * 64;
    int tid = threadIdx.x;
    #pragma unroll
    for (int it = 0; it < 8; it++) {
        int id = tid + it * 256;
        int row = id >> 5, cp = (id & 31) * 2;
        __half2 v = *reinterpret_cast<const __half2*>(s + (long long)(r0 + row) * C + c0 + cp);
        t[row][cp] = v.x; t[row][cp + 1] = v.y;
    }
    __syncthreads();
    #pragma unroll
    for (int it = 0; it < 8; it++) {
        int id = tid + it * 256;
        int cc = id >> 5, rp = (id & 31) * 2;
        __half2 v = { t[rp][cc], t[rp + 1][cc] };
        *reinterpret_cast<__half2*>(d + (long long)(c0 + cc) * R + r0 + rp) = v;
    }
}

// ---------------- launcher ----------------
extern "C" void kernel_launch(void* const* d_in, const int* in_sizes, int n_in,
                              void* d_out, int out_size)
{
    const float* x  = (const float*)d_in[0];
    const float* Wq = (const float*)d_in[1];
    const float* bq = (const float*)d_in[2];
    const float* Wk = (const float*)d_in[3];
    const float* bk = (const float*)d_in[4];
    const float* Wv = (const float*)d_in[5];
    const float* bv = (const float*)d_in[6];
    float* out = (float*)d_out;

    __half *xh, *xTh, *Gh, *WvHatT, *W2tmp, *W2Ts;
    float *WkHat, *bhat, *Y, *m, *mk, *mv, *S, *r;
    cudaGetSymbolAddress((void**)&xh, g_xh);
    cudaGetSymbolAddress((void**)&xTh, g_xTh);
    cudaGetSymbolAddress((void**)&Gh, g_Gh);
    cudaGetSymbolAddress((void**)&WkHat, g_WkHat);
    cudaGetSymbolAddress((void**)&WvHatT, g_WvHatT);
    cudaGetSymbolAddress((void**)&bhat, g_bhat);
    cudaGetSymbolAddress((void**)&Y, g_Y);
    cudaGetSymbolAddress((void**)&m, g_m);
    cudaGetSymbolAddress((void**)&mk, g_mk);
    cudaGetSymbolAddress((void**)&mv, g_mv);
    cudaGetSymbolAddress((void**)&S, g_S);
    cudaGetSymbolAddress((void**)&r, g_r);
    cudaGetSymbolAddress((void**)&W2tmp, g_W2tmp);
    cudaGetSymbolAddress((void**)&W2Ts, g_W2Ts);

    cudaFuncSetAttribute(gemm_hmma, cudaFuncAttributeMaxDynamicSharedMemorySize, DSMEM1);

    const long long dd = (long long)Dd * Dd;        // 1M
    const long long sd = (long long)Sq * Dd;        // 4M

    // 0) zeros; fused x prep (xh + xTh + colsum m); weight row-FFTs (+pad zero)
    zero_all<<<(Bsz * 513 * 2 + 255) / 256, 256>>>(S, m, mk, mv);
    prep_x<<<dim3(Dd / 64, Sq / 64, Bsz), 256>>>(x, xh, xTh, m);
    fft_rows<<<2 * Dd + 2, 256>>>(Wk, Wv, bk, bv, WkHat, WvHatT, bhat);

    // bias path: mk = m@Wk, mv = m@Wv
    gemv_mw<<<dim3(Dd / 256, 2, Dd / 256), 256>>>(Wk, Wv, m, mk, mv);

    // 1) Gram: G_b = xT_b @ xT_b^T  (M=N=1024, K=4096) -> fp16
    gemm_hmma<<<dim3(Dd / 128, Dd / 128, Bsz), 128, DSMEM1>>>(
        xTh, xTh, nullptr, nullptr, Gh, Dd, Sq, sd, sd, 0, dd);

    // 2) Y_b = G_b @ WvHat  (N=1152 = 513 Re + 513 Im + pad) -> fp32
    gemm_hmma<<<dim3(1152 / 128, Dd / 128, Bsz), 128, DSMEM1>>>(
        Gh, WvHatT, nullptr, Y, nullptr, 1152, Dd, dd, 0, 0, (long long)Dd * 1152);

    // 3) S[b][f] = sum_e WkHat[e][f] * Y[b][e][f]  (+ bias spectrum terms)
    dot_S<<<dim3(Dd / ECHUNK, Bsz), 256>>>(WkHat, Y, S);
    bias_S<<<Bsz, 256>>>(mk, mv, bhat, S);

    // 4) W2 rows (d<Dd) + r (d==Dd) via spectral unbind; transpose to [n][d]
    fft_w2<<<Dd + 1, 256>>>(Wq, bq, S, W2tmp, r);
    transpose_f16<<<dim3(Dd / 64, Dd / 64, Bsz), 256>>>(W2tmp, W2Ts, Dd, Dd, dd, dd);

    // 5) out_b = x_b @ W2_b + r_b  (fp32 out)
    gemm_hmma<<<dim3(Dd / 128, Sq / 128, Bsz), 128, DSMEM1>>>(
        xh, W2Ts, r, out, nullptr, Dd, Dd, sd, dd, Dd, sd);
}

// round 16
// speedup vs baseline: 1.3193x; 1.0626x over previous
#include <cuda_runtime.h>
#include <cuda_fp16.h>
#include <stdint.h>

#define Bsz 4
#define Sq  4096
#define Dd  1024
#define BS  (Bsz * Sq)   // 16384

// ---------------- scratch (device globals — allocation is forbidden) ----------------
__device__ __align__(256) __half g_xh[(long long)BS * Dd];          // x fp16 [t][d]
__device__ __align__(256) __half g_xTh[(long long)BS * Dd];         // x^T fp16 [b][d][t]
__device__ __align__(256) __half g_Gh[(long long)Bsz * Dd * Dd];    // Gram fp16 [b][e][e']
__device__ __align__(256) float  g_WkHat[(long long)Dd * 1026];     // [e][Re 513 | Im 513]
__device__ __align__(256) __half g_WvHatT[(long long)1152 * Dd];    // [f-comp][e] rows 0-512 Re, 513-1025 Im
__device__ __align__(256) float  g_bhat[2 * 1026];                  // bk-hat, bv-hat
__device__ __align__(256) float  g_Y[(long long)Bsz * Dd * 1152];   // G @ WvHat (fp32)
__device__ __align__(256) float  g_m[Bsz * Dd];
__device__ __align__(256) float  g_mk[Bsz * Dd];
__device__ __align__(256) float  g_mv[Bsz * Dd];
__device__ __align__(256) float  g_S[Bsz * 513 * 2];
__device__ __align__(256) float  g_r[Bsz * Dd];
__device__ __align__(256) __half g_W2tmp[(long long)Bsz * Dd * Dd]; // [b][d][n]
__device__ __align__(256) __half g_W2Ts[(long long)Bsz * Dd * Dd];  // [b][n][d]

// ---------------- PTX helpers ----------------
__device__ __forceinline__ uint32_t smem_u32(const void* p) {
    uint32_t a;
    asm("{ .reg .u64 t; cvta.to.shared.u64 t, %1; cvt.u32.u64 %0, t; }" : "=r"(a) : "l"(p));
    return a;
}
__device__ __forceinline__ void cp16(uint32_t dst, const void* src) {
    asm volatile("cp.async.cg.shared.global [%0], [%1], 16;" :: "r"(dst), "l"(src));
}
__device__ __forceinline__ void cp_commit() { asm volatile("cp.async.commit_group;" ::: "memory"); }
template<int N> __device__ __forceinline__ void cp_wait() {
    asm volatile("cp.async.wait_group %0;" :: "n"(N) : "memory");
}

__device__ __forceinline__ void ldsm_x4(uint32_t& r0, uint32_t& r1, uint32_t& r2, uint32_t& r3,
                                        uint32_t addr) {
    asm volatile("ldmatrix.sync.aligned.m8n8.x4.shared.b16 {%0,%1,%2,%3}, [%4];"
                 : "=r"(r0), "=r"(r1), "=r"(r2), "=r"(r3) : "r"(addr));
}
__device__ __forceinline__ void mma_fp16(float& c0, float& c1, float& c2, float& c3,
                                         uint32_t a0, uint32_t a1, uint32_t a2, uint32_t a3,
                                         uint32_t b0, uint32_t b1) {
    asm volatile(
        "mma.sync.aligned.m16n8k16.row.col.f32.f16.f16.f32 "
        "{%0,%1,%2,%3}, {%4,%5,%6,%7}, {%8,%9}, {%0,%1,%2,%3};"
        : "+f"(c0), "+f"(c1), "+f"(c2), "+f"(c3)
        : "r"(a0), "r"(a1), "r"(a2), "r"(a3), "r"(b0), "r"(b1));
}

// ---------------- fp16 HMMA GEMM (frozen since R12) ----------------
#define STG1 32768
#define DSMEM1 (3 * STG1)     // 98304

__global__ __launch_bounds__(128, 2) void gemm_hmma(
    const __half* __restrict__ Ah,
    const __half* __restrict__ Bs,
    const float* __restrict__ bias, float* __restrict__ Cf,
    __half* __restrict__ Ch,
    int N, int Ktot,
    long long sA, long long sB, long long sBias, long long sC)
{
    extern __shared__ __align__(128) char smem[];
    const int tid = threadIdx.x;
    const int wid = tid >> 5, lid = tid & 31;
    const int bz = blockIdx.z;
    const long long bm = (long long)blockIdx.y * 128;
    const long long bn = (long long)blockIdx.x * 128;

    const __half* gA0 = Ah + bz * sA + bm * Ktot;
    const __half* gB = Bs + bz * sB + bn * Ktot;
    const float* biasp = bias ? bias + bz * sBias : nullptr;

    const uint32_t sb = smem_u32(smem);
    const int wm = (wid & 1) * 64;
    const int wn = (wid >> 1) * 64;

    float acc[4][8][4];
    #pragma unroll
    for (int a = 0; a < 4; a++)
        #pragma unroll
        for (int b = 0; b < 8; b++)
            #pragma unroll
            for (int c = 0; c < 4; c++) acc[a][b][c] = 0.f;

    auto load_chunk = [&](int slot, int k0) {
        const uint32_t buf = sb + slot * STG1;
        #pragma unroll
        for (int it = 0; it < 8; it++) {
            int id = tid + it * 128;
            int r = id >> 3, c = id & 7;
            cp16(buf + r * 128 + (((c ^ r) & 7) << 4),
                 gA0 + (long long)r * Ktot + k0 + c * 8);
        }
        #pragma unroll
        for (int it = 0; it < 8; it++) {
            int id = tid + it * 128;
            int r = id >> 3, c = id & 7;
            cp16(buf + 16384 + r * 128 + ((c ^ (r & 7)) << 4),
                 gB + (long long)r * Ktot + k0 + c * 8);
        }
        cp_commit();
    };

    const int nc = Ktot >> 6;
    load_chunk(0, 0);
    load_chunk(1, 64);

    const int a_row = wm + (lid & 15);
    const int a_hi  = lid >> 4;
    const int b_row = wn + (lid & 7) + ((lid >> 4) & 1) * 8;
    const int b_hi  = (lid >> 3) & 1;

    uint32_t Af[2][4][4], Bf[2][4][4];
    auto ldsm_frags = [&](uint32_t buf, int kk, uint32_t A_[4][4], uint32_t B_[4][4]) {
        #pragma unroll
        for (int mb = 0; mb < 4; mb++) {
            int r = a_row + mb * 16;
            int c = kk * 2 + a_hi;
            ldsm_x4(A_[mb][0], A_[mb][1], A_[mb][2], A_[mb][3],
                    buf + r * 128 + ((c ^ (r & 7)) << 4));
        }
        #pragma unroll
        for (int nq = 0; nq < 4; nq++) {
            int r = b_row + nq * 16;
            int c = kk * 2 + b_hi;
            ldsm_x4(B_[nq][0], B_[nq][1], B_[nq][2], B_[nq][3],
                    buf + 16384 + r * 128 + ((c ^ (r & 7)) << 4));
        }
    };

    int slot = 0;
    for (int i = 0; i < nc; i++) {
        if (i + 1 < nc) cp_wait<1>(); else cp_wait<0>();
        __syncthreads();
        if (i + 2 < nc) {
            int ns = slot + 2; if (ns >= 3) ns -= 3;
            load_chunk(ns, (i + 2) << 6);
        }
        const uint32_t buf = sb + slot * STG1;
        ldsm_frags(buf, 0, Af[0], Bf[0]);
        #pragma unroll
        for (int kk = 0; kk < 4; kk++) {
            const int cur = kk & 1;
            if (kk < 3) ldsm_frags(buf, kk + 1, Af[cur ^ 1], Bf[cur ^ 1]);
            #pragma unroll
            for (int mb = 0; mb < 4; mb++)
                #pragma unroll
                for (int nq = 0; nq < 4; nq++)
                    #pragma unroll
                    for (int half = 0; half < 2; half++) {
                        float* c = acc[mb][nq * 2 + half];
                        mma_fp16(c[0], c[1], c[2], c[3],
                                 Af[cur][mb][0], Af[cur][mb][1], Af[cur][mb][2], Af[cur][mb][3],
                                 Bf[cur][nq][half * 2], Bf[cur][nq][half * 2 + 1]);
                    }
        }
        if (++slot == 3) slot = 0;
    }

    const int er = lid >> 2;
    const int ec = (lid & 3) * 2;
    #pragma unroll
    for (int mb = 0; mb < 4; mb++) {
        #pragma unroll
        for (int nb = 0; nb < 8; nb++) {
            const float* c = acc[mb][nb];
            long long col = bn + wn + nb * 8 + ec;
            float bx = 0.f, by = 0.f;
            if (biasp) { bx = biasp[col]; by = biasp[col + 1]; }
            long long r0 = bm + wm + mb * 16 + er;
            float v0 = c[0] + bx, v1 = c[1] + by;
            float v2 = c[2] + bx, v3 = c[3] + by;
            if (Cf) {
                float* Cb = Cf + bz * sC;
                *reinterpret_cast<float2*>(Cb + r0 * N + col) = make_float2(v0, v1);
                *reinterpret_cast<float2*>(Cb + (r0 + 8) * N + col) = make_float2(v2, v3);
            } else {
                __half2 s0 = { __float2half(v0), __float2half(v1) };
                __half2 s1 = { __float2half(v2), __float2half(v3) };
                __half* Hb = Ch + bz * sC;
                *reinterpret_cast<__half2*>(Hb + r0 * N + col) = s0;
                *reinterpret_cast<__half2*>(Hb + (r0 + 8) * N + col) = s1;
            }
        }
    }
}

// ---------------- FFT machinery (radix-4 Stockham, N=1024, 256 threads) ----------------
#define FPAD(i) ((i) + ((i) >> 5))

__device__ __forceinline__ void fft1024_stages(
    float* br0, float* bi0, float* br1, float* bi1,
    const float* twr, const float* twi, int tid, int inv)
{
    float *sr = br0, *si = bi0, *dr = br1, *di = bi1;
    const int Ls[5] = {256, 64, 16, 4, 1};
    const int Ms[5] = {1, 4, 16, 64, 256};
    #pragma unroll
    for (int st = 0; st < 5; st++) {
        const int l = Ls[st], m = Ms[st];
        int j = tid / m, k = tid - j * m;
        int ti = j * (256 / l);
        float w1r = twr[ti], w1i = twi[ti];
        float w2r = w1r * w1r - w1i * w1i, w2i = 2.f * w1r * w1i;
        float w3r = w2r * w1r - w2i * w1i, w3i = w2r * w1i + w2i * w1r;
        int i0 = k + m * j;
        float c0r = sr[FPAD(i0)],             c0i = si[FPAD(i0)];
        float c1r = sr[FPAD(i0 + m * l)],     c1i = si[FPAD(i0 + m * l)];
        float c2r = sr[FPAD(i0 + 2 * m * l)], c2i = si[FPAD(i0 + 2 * m * l)];
        float c3r = sr[FPAD(i0 + 3 * m * l)], c3i = si[FPAD(i0 + 3 * m * l)];
        float t0r = c0r + c2r, t0i = c0i + c2i;
        float t1r = c0r - c2r, t1i = c0i - c2i;
        float t2r = c1r + c3r, t2i = c1i + c3i;
        float t3r = c1r - c3r, t3i = c1i - c3i;
        float u0r = t0r + t2r, u0i = t0i + t2i;
        float u2r = t0r - t2r, u2i = t0i - t2i;
        float u1r, u1i, u3r, u3i;
        if (!inv) { u1r = t1r + t3i; u1i = t1i - t3r; u3r = t1r - t3i; u3i = t1i + t3r; }
        else      { u1r = t1r - t3i; u1i = t1i + t3r; u3r = t1r + t3i; u3i = t1i - t3r; }
        int o = k + 4 * m * j;
        dr[FPAD(o)]         = u0r;                    di[FPAD(o)]         = u0i;
        dr[FPAD(o + m)]     = w1r * u1r - w1i * u1i;  di[FPAD(o + m)]     = w1r * u1i + w1i * u1r;
        dr[FPAD(o + 2 * m)] = w2r * u2r - w2i * u2i;  di[FPAD(o + 2 * m)] = w2r * u2i + w2i * u2r;
        dr[FPAD(o + 3 * m)] = w3r * u3r - w3i * u3i;  di[FPAD(o + 3 * m)] = w3r * u3i + w3i * u3r;
        __syncthreads();
        float* t;
        t = sr; sr = dr; dr = t;
        t = si; si = di; di = t;
    }
}

// ---------------- fft_rows: FFT of Wk rows, Wv rows, bk, bv (+ WvHatT pad zero) ----------------
__global__ __launch_bounds__(256) void fft_rows(
    const float* __restrict__ Wk, const float* __restrict__ Wv,
    const float* __restrict__ bk, const float* __restrict__ bv,
    float* __restrict__ WkHat, __half* __restrict__ WvHatT, float* __restrict__ bhat)
{
    __shared__ float Ar0[1056], Ai0[1056], Ar1[1056], Ai1[1056];
    __shared__ float twr[256], twi[256];
    const int tid = threadIdx.x;
    const int c = blockIdx.x;
    if (c < 126) {   // zero pad rows 1026..1151 of WvHatT
        __half2 z = { __float2half(0.f), __float2half(0.f) };
        __half2* p = reinterpret_cast<__half2*>(WvHatT + (long long)(1026 + c) * Dd);
        p[tid] = z;
        p[tid + 256] = z;
    }
    {
        float sv, cv;
        __sincosf(-6.28318530717958647692f * (float)tid / 1024.f, &sv, &cv);
        twr[tid] = cv; twi[tid] = sv;
    }
    const float* row;
    if (c < Dd) row = Wk + (long long)c * Dd;
    else if (c < 2 * Dd) row = Wv + (long long)(c - Dd) * Dd;
    else row = (c == 2 * Dd) ? bk : bv;

    #pragma unroll
    for (int q = 0; q < 4; q++) {
        int i = tid + 256 * q;
        Ar0[FPAD(i)] = row[i];
        Ai0[FPAD(i)] = 0.f;
    }
    __syncthreads();
    fft1024_stages(Ar0, Ai0, Ar1, Ai1, twr, twi, tid, 0);

    auto store = [&](int f, float Re, float Im) {
        if (c < Dd) {
            WkHat[(long long)c * 1026 + f] = Re;
            WkHat[(long long)c * 1026 + 513 + f] = Im;
        } else if (c < 2 * Dd) {
            int e = c - Dd;
            WvHatT[(long long)f * Dd + e] = __float2half(Re);
            WvHatT[(long long)(513 + f) * Dd + e] = __float2half(Im);
        } else {
            int o = (c - 2 * Dd) * 1026;
            bhat[o + f] = Re;
            bhat[o + 513 + f] = Im;
        }
    };
    #pragma unroll
    for (int h = 0; h < 2; h++) {
        int f = tid + h * 256;
        store(f, Ar1[FPAD(f)], Ai1[FPAD(f)]);
    }
    if (tid == 0) store(512, Ar1[FPAD(512)], Ai1[FPAD(512)]);
}

// ---------------- dot: S[b][f] = sum_e WkHat[e][f] * Y[b][e][f]  (complex) ----------------
#define ECHUNK 16
__global__ __launch_bounds__(256) void dot_S(
    const float* __restrict__ WkHat, const float* __restrict__ Y, float* __restrict__ S)
{
    const int b = blockIdx.y, tid = threadIdx.x;
    const int e0 = blockIdx.x * ECHUNK;
    const float* Yb = Y + (long long)b * Dd * 1152;
    float sr0 = 0, si0 = 0, sr1 = 0, si1 = 0, sr2 = 0, si2 = 0;
    for (int e = e0; e < e0 + ECHUNK; e++) {
        const float* w = WkHat + (long long)e * 1026;
        const float* y = Yb + (long long)e * 1152;
        {
            int f = tid;
            float Wr = w[f], Wi = w[513 + f], Yr = y[f], Yi = y[513 + f];
            sr0 += Wr * Yr - Wi * Yi;  si0 += Wr * Yi + Wi * Yr;
        }
        {
            int f = tid + 256;
            float Wr = w[f], Wi = w[513 + f], Yr = y[f], Yi = y[513 + f];
            sr1 += Wr * Yr - Wi * Yi;  si1 += Wr * Yi + Wi * Yr;
        }
        if (tid == 0) {
            int f = 512;
            float Wr = w[f], Wi = w[513 + f], Yr = y[f], Yi = y[513 + f];
            sr2 += Wr * Yr - Wi * Yi;  si2 += Wr * Yi + Wi * Yr;
        }
    }
    float* Sb = S + b * 513 * 2;
    atomicAdd(&Sb[tid * 2 + 0], sr0);        atomicAdd(&Sb[tid * 2 + 1], si0);
    atomicAdd(&Sb[(tid + 256) * 2 + 0], sr1); atomicAdd(&Sb[(tid + 256) * 2 + 1], si1);
    if (tid == 0) { atomicAdd(&Sb[512 * 2 + 0], sr2); atomicAdd(&Sb[512 * 2 + 1], si2); }
}

// ---------------- bias terms: S += bhv*Mk + bhk*Mv + T*bhk*bhv ----------------
__global__ __launch_bounds__(256) void bias_S(
    const float* __restrict__ mk, const float* __restrict__ mv,
    const float* __restrict__ bhat, float* __restrict__ S)
{
    __shared__ float Ar0[1056], Ai0[1056], Ar1[1056], Ai1[1056];
    __shared__ float twr[256], twi[256];
    const int b = blockIdx.x, tid = threadIdx.x;
    {
        float sv, cv;
        __sincosf(-6.28318530717958647692f * (float)tid / 1024.f, &sv, &cv);
        twr[tid] = cv; twi[tid] = sv;
    }
    #pragma unroll
    for (int q = 0; q < 4; q++) {
        int i = tid + 256 * q;
        Ar0[FPAD(i)] = mk[b * Dd + i];
        Ai0[FPAD(i)] = 0.f;
    }
    __syncthreads();
    fft1024_stages(Ar0, Ai0, Ar1, Ai1, twr, twi, tid, 0);
    float Mkr0 = Ar1[FPAD(tid)],       Mki0 = Ai1[FPAD(tid)];
    float Mkr1 = Ar1[FPAD(tid + 256)], Mki1 = Ai1[FPAD(tid + 256)];
    float Mkr2 = 0.f, Mki2 = 0.f;
    if (tid == 0) { Mkr2 = Ar1[FPAD(512)]; Mki2 = Ai1[FPAD(512)]; }
    __syncthreads();
    #pragma unroll
    for (int q = 0; q < 4; q++) {
        int i = tid + 256 * q;
        Ar0[FPAD(i)] = mv[b * Dd + i];
        Ai0[FPAD(i)] = 0.f;
    }
    __syncthreads();
    fft1024_stages(Ar0, Ai0, Ar1, Ai1, twr, twi, tid, 0);
    float Mvr0 = Ar1[FPAD(tid)],       Mvi0 = Ai1[FPAD(tid)];
    float Mvr1 = Ar1[FPAD(tid + 256)], Mvi1 = Ai1[FPAD(tid + 256)];
    float Mvr2 = 0.f, Mvi2 = 0.f;
    if (tid == 0) { Mvr2 = Ar1[FPAD(512)]; Mvi2 = Ai1[FPAD(512)]; }

    auto add = [&](int f, float Mkr, float Mki, float Mvr, float Mvi) {
        float bkr = bhat[f], bki = bhat[513 + f];
        float bvr = bhat[1026 + f], bvi = bhat[1026 + 513 + f];
        float Sr = bvr * Mkr - bvi * Mki + bkr * Mvr - bki * Mvi
                 + (float)Sq * (bkr * bvr - bki * bvi);
        float Si = bvr * Mki + bvi * Mkr + bkr * Mvi + bki * Mvr
                 + (float)Sq * (bkr * bvi + bki * bvr);
        S[b * 1026 + 2 * f]     += Sr;
        S[b * 1026 + 2 * f + 1] += Si;
    };
    add(tid, Mkr0, Mki0, Mvr0, Mvi0);
    add(tid + 256, Mkr1, Mki1, Mvr1, Mvi1);
    if (tid == 0) add(512, Mkr2, Mki2, Mvr2, Mvi2);
}

// ---------------- fft_w2: W2 rows (d<Dd) + r (d==Dd) via spectral unbind ----------------
__global__ __launch_bounds__(256) void fft_w2(
    const float* __restrict__ Wq, const float* __restrict__ bq,
    const float* __restrict__ Sacc,
    __half* __restrict__ W2tmp, float* __restrict__ r)
{
    __shared__ float Ar0[1056], Ai0[1056], Ar1[1056], Ai1[1056];
    __shared__ float twf_r[256], twf_i[256], twb_r[256], twb_i[256];
    const int tid = threadIdx.x;
    const int d = blockIdx.x;
    {
        float sv, cv;
        __sincosf(-6.28318530717958647692f * (float)tid / 1024.f, &sv, &cv);
        twf_r[tid] = cv; twf_i[tid] = sv;
        twb_r[tid] = cv; twb_i[tid] = -sv;
    }
    const float* wrow = (d < Dd) ? (Wq + (long long)d * Dd) : bq;
    #pragma unroll
    for (int q = 0; q < 4; q++) {
        int i = tid + 256 * q;
        Ar0[FPAD(i)] = wrow[i];
        Ai0[FPAD(i)] = 0.f;
    }
    __syncthreads();
    fft1024_stages(Ar0, Ai0, Ar1, Ai1, twf_r, twf_i, tid, 0);

    float Wr[4], Wi[4];
    #pragma unroll
    for (int q = 0; q < 4; q++) {
        int f = tid + 256 * q;
        Wr[q] = Ar1[FPAD(f)];
        Wi[q] = Ai1[FPAD(f)];
    }

    for (int b = 0; b < Bsz; b++) {
        const float* Sb = Sacc + b * 513 * 2;
        #pragma unroll
        for (int q = 0; q < 4; q++) {
            int f = tid + 256 * q;
            float Sr, Si;
            if (f <= 512) { Sr = Sb[f * 2]; Si = Sb[f * 2 + 1]; }
            else          { Sr = Sb[(1024 - f) * 2]; Si = -Sb[(1024 - f) * 2 + 1]; }
            Ar0[FPAD(f)] = Sr * Wr[q] + Si * Wi[q];
            Ai0[FPAD(f)] = Si * Wr[q] - Sr * Wi[q];
        }
        __syncthreads();
        fft1024_stages(Ar0, Ai0, Ar1, Ai1, twb_r, twb_i, tid, 1);
        if (d < Dd) {
            __half* dst = W2tmp + ((long long)b << 20) + ((long long)d << 10);
            #pragma unroll
            for (int q = 0; q < 4; q++) {
                int i = tid + 256 * q;
                dst[i] = __float2half(Ar1[FPAD(i)] * (1.f / 1024.f));
            }
        } else {
            float* dst = r + b * Dd;
            #pragma unroll
            for (int q = 0; q < 4; q++) {
                int i = tid + 256 * q;
                dst[i] = Ar1[FPAD(i)] * (1.f / 1024.f);
            }
        }
    }
}

// ---------------- fused x prep: xh (same layout) + xTh (transposed) + colsum m ----------------
__global__ __launch_bounds__(256) void prep_x(
    const float* __restrict__ x, __half* __restrict__ xh, __half* __restrict__ xTh,
    float* __restrict__ m)
{
    __shared__ __half th[64][65];
    const int b = blockIdx.z;
    const int t0 = blockIdx.y * 64, d0 = blockIdx.x * 64;
    const int tid = threadIdx.x;
    const long long xbase = ((long long)b * Sq + t0) * Dd + d0;
    const int c = tid & 63, rq = tid >> 6;
    float csum = 0.f;
    #pragma unroll
    for (int k = 0; k < 16; k++) {
        int rr = rq + k * 4;
        float v = x[xbase + (long long)rr * Dd + c];
        __half h = __float2half(v);
        xh[xbase + (long long)rr * Dd + c] = h;
        th[rr][c] = h;
        csum += v;
    }
    atomicAdd(&m[b * Dd + d0 + c], csum);
    __syncthreads();
    const long long obase = ((long long)b * Dd + d0) * Sq + t0;
    #pragma unroll
    for (int it = 0; it < 8; it++) {
        int id = tid + it * 256;
        int cc = id >> 5, rp = (id & 31) * 2;
        __half2 v = { th[rp][cc], th[rp + 1][cc] };
        *reinterpret_cast<__half2*>(xTh + obase + (long long)cc * Sq + rp) = v;
    }
}

// ---------------- misc small kernels ----------------
__global__ void zero_all(float* S, float* m, float* mk, float* mv)
{
    int i = blockIdx.x * 256 + threadIdx.x;
    if (i < Bsz * 513 * 2) S[i] = 0.f;
    if (i < Bsz * Dd) { m[i] = 0.f; mk[i] = 0.f; mv[i] = 0.f; }
}

// mk = m@Wk ; mv = m@Wv — e-chunked (64 rows/block), 128 blocks, atomics
__global__ void gemv_mw(const float* __restrict__ Wk, const float* __restrict__ Wv,
                        const float* __restrict__ m,
                        float* __restrict__ mk, float* __restrict__ mv)
{
    int d = blockIdx.x * 256 + threadIdx.x;
    int e0 = blockIdx.z * 64;
    const float* W = blockIdx.y ? Wv : Wk;
    float* o = blockIdx.y ? mv : mk;
    float a0 = 0, a1 = 0, a2 = 0, a3 = 0;
    #pragma unroll 4
    for (int e = e0; e < e0 + 64; e++) {
        float w = W[(long long)e * Dd + d];
        a0 += m[e] * w;
        a1 += m[Dd + e] * w;
        a2 += m[2 * Dd + e] * w;
        a3 += m[3 * Dd + e] * w;
    }
    atomicAdd(&o[d], a0);
    atomicAdd(&o[Dd + d], a1);
    atomicAdd(&o[2 * Dd + d], a2);
    atomicAdd(&o[3 * Dd + d], a3);
}

__global__ void transpose_f16(const __half* __restrict__ s, __half* __restrict__ d,
                              int R, int C, long long sIn, long long sOut)
{
    __shared__ __half t[64][65];
    int b = blockIdx.z;
    s += (long long)b * sIn; d += (long long)b * sOut;
    int c0 = blockIdx.x * 64, r0 = blockIdx.y * 64;
    int tid = threadIdx.x;
    #pragma unroll
    for (int it = 0; it < 8; it++) {
        int id = tid + it * 256;
        int row = id >> 5, cp = (id & 31) * 2;
        __half2 v = *reinterpret_cast<const __half2*>(s + (long long)(r0 + row) * C + c0 + cp);
        t[row][cp] = v.x; t[row][cp + 1] = v.y;
    }
    __syncthreads();
    #pragma unroll
    for (int it = 0; it < 8; it++) {
        int id = tid + it * 256;
        int cc = id >> 5, rp = (id & 31) * 2;
        __half2 v = { t[rp][cc], t[rp + 1][cc] };
        *reinterpret_cast<__half2*>(d + (long long)(c0 + cc) * R + r0 + rp) = v;
    }
}

// ---------------- launcher ----------------
extern "C" void kernel_launch(void* const* d_in, const int* in_sizes, int n_in,
                              void* d_out, int out_size)
{
    const float* x  = (const float*)d_in[0];
    const float* Wq = (const float*)d_in[1];
    const float* bq = (const float*)d_in[2];
    const float* Wk = (const float*)d_in[3];
    const float* bk = (const float*)d_in[4];
    const float* Wv = (const float*)d_in[5];
    const float* bv = (const float*)d_in[6];
    float* out = (float*)d_out;

    __half *xh, *xTh, *Gh, *WvHatT, *W2tmp, *W2Ts;
    float *WkHat, *bhat, *Y, *m, *mk, *mv, *S, *r;
    cudaGetSymbolAddress((void**)&xh, g_xh);
    cudaGetSymbolAddress((void**)&xTh, g_xTh);
    cudaGetSymbolAddress((void**)&Gh, g_Gh);
    cudaGetSymbolAddress((void**)&WkHat, g_WkHat);
    cudaGetSymbolAddress((void**)&WvHatT, g_WvHatT);
    cudaGetSymbolAddress((void**)&bhat, g_bhat);
    cudaGetSymbolAddress((void**)&Y, g_Y);
    cudaGetSymbolAddress((void**)&m, g_m);
    cudaGetSymbolAddress((void**)&mk, g_mk);
    cudaGetSymbolAddress((void**)&mv, g_mv);
    cudaGetSymbolAddress((void**)&S, g_S);
    cudaGetSymbolAddress((void**)&r, g_r);
    cudaGetSymbolAddress((void**)&W2tmp, g_W2tmp);
    cudaGetSymbolAddress((void**)&W2Ts, g_W2Ts);

    cudaFuncSetAttribute(gemm_hmma, cudaFuncAttributeMaxDynamicSharedMemorySize, DSMEM1);

    const long long dd = (long long)Dd * Dd;        // 1M
    const long long sd = (long long)Sq * Dd;        // 4M

    // 0) zeros; fused x prep (xh + xTh + colsum m); weight row-FFTs (+pad zero)
    zero_all<<<(Bsz * 513 * 2 + 255) / 256, 256>>>(S, m, mk, mv);
    prep_x<<<dim3(Dd / 64, Sq / 64, Bsz), 256>>>(x, xh, xTh, m);
    fft_rows<<<2 * Dd + 2, 256>>>(Wk, Wv, bk, bv, WkHat, WvHatT, bhat);

    // bias path: mk = m@Wk, mv = m@Wv  (128 blocks, latency-covered)
    gemv_mw<<<dim3(Dd / 256, 2, Dd / 64), 256>>>(Wk, Wv, m, mk, mv);

    // 1) Gram: G_b = xT_b @ xT_b^T  (M=N=1024, K=4096) -> fp16
    gemm_hmma<<<dim3(Dd / 128, Dd / 128, Bsz), 128, DSMEM1>>>(
        xTh, xTh, nullptr, nullptr, Gh, Dd, Sq, sd, sd, 0, dd);

    // 2) Y_b = G_b @ WvHat  (N=1152 = 513 Re + 513 Im + pad) -> fp32
    gemm_hmma<<<dim3(1152 / 128, Dd / 128, Bsz), 128, DSMEM1>>>(
        Gh, WvHatT, nullptr, Y, nullptr, 1152, Dd, dd, 0, 0, (long long)Dd * 1152);

    // 3) S[b][f] = sum_e WkHat[e][f] * Y[b][e][f]  (+ bias spectrum terms)
    dot_S<<<dim3(Dd / ECHUNK, Bsz), 256>>>(WkHat, Y, S);
    bias_S<<<Bsz, 256>>>(mk, mv, bhat, S);

    // 4) W2 rows (d<Dd) + r (d==Dd) via spectral unbind; transpose to [n][d]
    fft_w2<<<Dd + 1, 256>>>(Wq, bq, S, W2tmp, r);
    transpose_f16<<<dim3(Dd / 64, Dd / 64, Bsz), 256>>>(W2tmp, W2Ts, Dd, Dd, dd, dd);

    // 5) out_b = x_b @ W2_b + r_b  (fp32 out)
    gemm_hmma<<<dim3(Dd / 128, Sq / 128, Bsz), 128, DSMEM1>>>(
        xh, W2Ts, r, out, nullptr, Dd, Dd, sd, dd, Dd, sd);
}

// round 17
// speedup vs baseline: 1.3486x; 1.0222x over previous
#include <cuda_runtime.h>
#include <cuda_fp16.h>
#include <stdint.h>

#define Bsz 4
#define Sq  4096
#define Dd  1024
#define BS  (Bsz * Sq)   // 16384

// ---------------- scratch (device globals — allocation is forbidden) ----------------
__device__ __align__(256) __half g_xh[(long long)BS * Dd];          // x fp16 [t][d]
__device__ __align__(256) __half g_xTh[(long long)BS * Dd];         // x^T fp16 [b][d][t]
__device__ __align__(256) __half g_Gh[(long long)Bsz * Dd * Dd];    // Gram fp16 [b][e][e']
__device__ __align__(256) float  g_WkHat[(long long)Dd * 1026];     // [e][Re 513 | Im 513]
__device__ __align__(256) __half g_WvHatT[(long long)1152 * Dd];    // [f-comp][e] rows 0-512 Re, 513-1025 Im
__device__ __align__(256) float  g_bhat[2 * 1026];                  // bk-hat, bv-hat
__device__ __align__(256) float  g_Y[(long long)Bsz * Dd * 1152];   // G @ WvHat (fp32)
__device__ __align__(256) float  g_m[Bsz * Dd];
__device__ __align__(256) float  g_mk[Bsz * Dd];
__device__ __align__(256) float  g_mv[Bsz * Dd];
__device__ __align__(256) float  g_S[Bsz * 513 * 2];
__device__ __align__(256) float  g_r[Bsz * Dd];
__device__ __align__(256) __half g_W2tmp[(long long)Bsz * Dd * Dd]; // [b][d][n]
__device__ __align__(256) __half g_W2Ts[(long long)Bsz * Dd * Dd];  // [b][n][d]

// ---------------- PTX helpers ----------------
__device__ __forceinline__ uint32_t smem_u32(const void* p) {
    uint32_t a;
    asm("{ .reg .u64 t; cvta.to.shared.u64 t, %1; cvt.u32.u64 %0, t; }" : "=r"(a) : "l"(p));
    return a;
}
__device__ __forceinline__ void cp16(uint32_t dst, const void* src) {
    asm volatile("cp.async.cg.shared.global [%0], [%1], 16;" :: "r"(dst), "l"(src));
}
__device__ __forceinline__ void cp_commit() { asm volatile("cp.async.commit_group;" ::: "memory"); }
template<int N> __device__ __forceinline__ void cp_wait() {
    asm volatile("cp.async.wait_group %0;" :: "n"(N) : "memory");
}

__device__ __forceinline__ void ldsm_x4(uint32_t& r0, uint32_t& r1, uint32_t& r2, uint32_t& r3,
                                        uint32_t addr) {
    asm volatile("ldmatrix.sync.aligned.m8n8.x4.shared.b16 {%0,%1,%2,%3}, [%4];"
                 : "=r"(r0), "=r"(r1), "=r"(r2), "=r"(r3) : "r"(addr));
}
__device__ __forceinline__ void mma_fp16(float& c0, float& c1, float& c2, float& c3,
                                         uint32_t a0, uint32_t a1, uint32_t a2, uint32_t a3,
                                         uint32_t b0, uint32_t b1) {
    asm volatile(
        "mma.sync.aligned.m16n8k16.row.col.f32.f16.f16.f32 "
        "{%0,%1,%2,%3}, {%4,%5,%6,%7}, {%8,%9}, {%0,%1,%2,%3};"
        : "+f"(c0), "+f"(c1), "+f"(c2), "+f"(c3)
        : "r"(a0), "r"(a1), "r"(a2), "r"(a3), "r"(b0), "r"(b1));
}

// ---------------- fp16 HMMA GEMM (frozen since R12) ----------------
#define STG1 32768
#define DSMEM1 (3 * STG1)     // 98304

__global__ __launch_bounds__(128, 2) void gemm_hmma(
    const __half* __restrict__ Ah,
    const __half* __restrict__ Bs,
    const float* __restrict__ bias, float* __restrict__ Cf,
    __half* __restrict__ Ch,
    int N, int Ktot,
    long long sA, long long sB, long long sBias, long long sC)
{
    extern __shared__ __align__(128) char smem[];
    const int tid = threadIdx.x;
    const int wid = tid >> 5, lid = tid & 31;
    const int bz = blockIdx.z;
    const long long bm = (long long)blockIdx.y * 128;
    const long long bn = (long long)blockIdx.x * 128;

    const __half* gA0 = Ah + bz * sA + bm * Ktot;
    const __half* gB = Bs + bz * sB + bn * Ktot;
    const float* biasp = bias ? bias + bz * sBias : nullptr;

    const uint32_t sb = smem_u32(smem);
    const int wm = (wid & 1) * 64;
    const int wn = (wid >> 1) * 64;

    float acc[4][8][4];
    #pragma unroll
    for (int a = 0; a < 4; a++)
        #pragma unroll
        for (int b = 0; b < 8; b++)
            #pragma unroll
            for (int c = 0; c < 4; c++) acc[a][b][c] = 0.f;

    auto load_chunk = [&](int slot, int k0) {
        const uint32_t buf = sb + slot * STG1;
        #pragma unroll
        for (int it = 0; it < 8; it++) {
            int id = tid + it * 128;
            int r = id >> 3, c = id & 7;
            cp16(buf + r * 128 + (((c ^ r) & 7) << 4),
                 gA0 + (long long)r * Ktot + k0 + c * 8);
        }
        #pragma unroll
        for (int it = 0; it < 8; it++) {
            int id = tid + it * 128;
            int r = id >> 3, c = id & 7;
            cp16(buf + 16384 + r * 128 + ((c ^ (r & 7)) << 4),
                 gB + (long long)r * Ktot + k0 + c * 8);
        }
        cp_commit();
    };

    const int nc = Ktot >> 6;
    load_chunk(0, 0);
    load_chunk(1, 64);

    const int a_row = wm + (lid & 15);
    const int a_hi  = lid >> 4;
    const int b_row = wn + (lid & 7) + ((lid >> 4) & 1) * 8;
    const int b_hi  = (lid >> 3) & 1;

    uint32_t Af[2][4][4], Bf[2][4][4];
    auto ldsm_frags = [&](uint32_t buf, int kk, uint32_t A_[4][4], uint32_t B_[4][4]) {
        #pragma unroll
        for (int mb = 0; mb < 4; mb++) {
            int r = a_row + mb * 16;
            int c = kk * 2 + a_hi;
            ldsm_x4(A_[mb][0], A_[mb][1], A_[mb][2], A_[mb][3],
                    buf + r * 128 + ((c ^ (r & 7)) << 4));
        }
        #pragma unroll
        for (int nq = 0; nq < 4; nq++) {
            int r = b_row + nq * 16;
            int c = kk * 2 + b_hi;
            ldsm_x4(B_[nq][0], B_[nq][1], B_[nq][2], B_[nq][3],
                    buf + 16384 + r * 128 + ((c ^ (r & 7)) << 4));
        }
    };

    int slot = 0;
    for (int i = 0; i < nc; i++) {
        if (i + 1 < nc) cp_wait<1>(); else cp_wait<0>();
        __syncthreads();
        if (i + 2 < nc) {
            int ns = slot + 2; if (ns >= 3) ns -= 3;
            load_chunk(ns, (i + 2) << 6);
        }
        const uint32_t buf = sb + slot * STG1;
        ldsm_frags(buf, 0, Af[0], Bf[0]);
        #pragma unroll
        for (int kk = 0; kk < 4; kk++) {
            const int cur = kk & 1;
            if (kk < 3) ldsm_frags(buf, kk + 1, Af[cur ^ 1], Bf[cur ^ 1]);
            #pragma unroll
            for (int mb = 0; mb < 4; mb++)
                #pragma unroll
                for (int nq = 0; nq < 4; nq++)
                    #pragma unroll
                    for (int half = 0; half < 2; half++) {
                        float* c = acc[mb][nq * 2 + half];
                        mma_fp16(c[0], c[1], c[2], c[3],
                                 Af[cur][mb][0], Af[cur][mb][1], Af[cur][mb][2], Af[cur][mb][3],
                                 Bf[cur][nq][half * 2], Bf[cur][nq][half * 2 + 1]);
                    }
        }
        if (++slot == 3) slot = 0;
    }

    const int er = lid >> 2;
    const int ec = (lid & 3) * 2;
    #pragma unroll
    for (int mb = 0; mb < 4; mb++) {
        #pragma unroll
        for (int nb = 0; nb < 8; nb++) {
            const float* c = acc[mb][nb];
            long long col = bn + wn + nb * 8 + ec;
            float bx = 0.f, by = 0.f;
            if (biasp) { bx = biasp[col]; by = biasp[col + 1]; }
            long long r0 = bm + wm + mb * 16 + er;
            float v0 = c[0] + bx, v1 = c[1] + by;
            float v2 = c[2] + bx, v3 = c[3] + by;
            if (Cf) {
                float* Cb = Cf + bz * sC;
                *reinterpret_cast<float2*>(Cb + r0 * N + col) = make_float2(v0, v1);
                *reinterpret_cast<float2*>(Cb + (r0 + 8) * N + col) = make_float2(v2, v3);
            } else {
                __half2 s0 = { __float2half(v0), __float2half(v1) };
                __half2 s1 = { __float2half(v2), __float2half(v3) };
                __half* Hb = Ch + bz * sC;
                *reinterpret_cast<__half2*>(Hb + r0 * N + col) = s0;
                *reinterpret_cast<__half2*>(Hb + (r0 + 8) * N + col) = s1;
            }
        }
    }
}

// ---------------- FFT machinery (radix-4 Stockham, N=1024, 256 threads) ----------------
#define FPAD(i) ((i) + ((i) >> 5))

__device__ __forceinline__ void fft1024_stages(
    float* br0, float* bi0, float* br1, float* bi1,
    const float* twr, const float* twi, int tid, int inv)
{
    float *sr = br0, *si = bi0, *dr = br1, *di = bi1;
    const int Ls[5] = {256, 64, 16, 4, 1};
    const int Ms[5] = {1, 4, 16, 64, 256};
    #pragma unroll
    for (int st = 0; st < 5; st++) {
        const int l = Ls[st], m = Ms[st];
        int j = tid / m, k = tid - j * m;
        int ti = j * (256 / l);
        float w1r = twr[ti], w1i = twi[ti];
        float w2r = w1r * w1r - w1i * w1i, w2i = 2.f * w1r * w1i;
        float w3r = w2r * w1r - w2i * w1i, w3i = w2r * w1i + w2i * w1r;
        int i0 = k + m * j;
        float c0r = sr[FPAD(i0)],             c0i = si[FPAD(i0)];
        float c1r = sr[FPAD(i0 + m * l)],     c1i = si[FPAD(i0 + m * l)];
        float c2r = sr[FPAD(i0 + 2 * m * l)], c2i = si[FPAD(i0 + 2 * m * l)];
        float c3r = sr[FPAD(i0 + 3 * m * l)], c3i = si[FPAD(i0 + 3 * m * l)];
        float t0r = c0r + c2r, t0i = c0i + c2i;
        float t1r = c0r - c2r, t1i = c0i - c2i;
        float t2r = c1r + c3r, t2i = c1i + c3i;
        float t3r = c1r - c3r, t3i = c1i - c3i;
        float u0r = t0r + t2r, u0i = t0i + t2i;
        float u2r = t0r - t2r, u2i = t0i - t2i;
        float u1r, u1i, u3r, u3i;
        if (!inv) { u1r = t1r + t3i; u1i = t1i - t3r; u3r = t1r - t3i; u3i = t1i + t3r; }
        else      { u1r = t1r - t3i; u1i = t1i + t3r; u3r = t1r + t3i; u3i = t1i - t3r; }
        int o = k + 4 * m * j;
        dr[FPAD(o)]         = u0r;                    di[FPAD(o)]         = u0i;
        dr[FPAD(o + m)]     = w1r * u1r - w1i * u1i;  di[FPAD(o + m)]     = w1r * u1i + w1i * u1r;
        dr[FPAD(o + 2 * m)] = w2r * u2r - w2i * u2i;  di[FPAD(o + 2 * m)] = w2r * u2i + w2i * u2r;
        dr[FPAD(o + 3 * m)] = w3r * u3r - w3i * u3i;  di[FPAD(o + 3 * m)] = w3r * u3i + w3i * u3r;
        __syncthreads();
        float* t;
        t = sr; sr = dr; dr = t;
        t = si; si = di; di = t;
    }
}

// ---------------- fft_rows: FFT of Wk rows, Wv rows, bk, bv (+ WvHatT pad zero) ----------------
__global__ __launch_bounds__(256) void fft_rows(
    const float* __restrict__ Wk, const float* __restrict__ Wv,
    const float* __restrict__ bk, const float* __restrict__ bv,
    float* __restrict__ WkHat, __half* __restrict__ WvHatT, float* __restrict__ bhat)
{
    __shared__ float Ar0[1056], Ai0[1056], Ar1[1056], Ai1[1056];
    __shared__ float twr[256], twi[256];
    const int tid = threadIdx.x;
    const int c = blockIdx.x;
    if (c < 126) {   // zero pad rows 1026..1151 of WvHatT
        __half2 z = { __float2half(0.f), __float2half(0.f) };
        __half2* p = reinterpret_cast<__half2*>(WvHatT + (long long)(1026 + c) * Dd);
        p[tid] = z;
        p[tid + 256] = z;
    }
    {
        float sv, cv;
        __sincosf(-6.28318530717958647692f * (float)tid / 1024.f, &sv, &cv);
        twr[tid] = cv; twi[tid] = sv;
    }
    const float* row;
    if (c < Dd) row = Wk + (long long)c * Dd;
    else if (c < 2 * Dd) row = Wv + (long long)(c - Dd) * Dd;
    else row = (c == 2 * Dd) ? bk : bv;

    #pragma unroll
    for (int q = 0; q < 4; q++) {
        int i = tid + 256 * q;
        Ar0[FPAD(i)] = row[i];
        Ai0[FPAD(i)] = 0.f;
    }
    __syncthreads();
    fft1024_stages(Ar0, Ai0, Ar1, Ai1, twr, twi, tid, 0);

    auto store = [&](int f, float Re, float Im) {
        if (c < Dd) {
            WkHat[(long long)c * 1026 + f] = Re;
            WkHat[(long long)c * 1026 + 513 + f] = Im;
        } else if (c < 2 * Dd) {
            int e = c - Dd;
            WvHatT[(long long)f * Dd + e] = __float2half(Re);
            WvHatT[(long long)(513 + f) * Dd + e] = __float2half(Im);
        } else {
            int o = (c - 2 * Dd) * 1026;
            bhat[o + f] = Re;
            bhat[o + 513 + f] = Im;
        }
    };
    #pragma unroll
    for (int h = 0; h < 2; h++) {
        int f = tid + h * 256;
        store(f, Ar1[FPAD(f)], Ai1[FPAD(f)]);
    }
    if (tid == 0) store(512, Ar1[FPAD(512)], Ai1[FPAD(512)]);
}

// ---------------- dot: S[b][f] = sum_e WkHat[e][f] * Y[b][e][f]  (complex) ----------------
#define ECHUNK 8
__global__ __launch_bounds__(256) void dot_S(
    const float* __restrict__ WkHat, const float* __restrict__ Y, float* __restrict__ S)
{
    const int b = blockIdx.y, tid = threadIdx.x;
    const int e0 = blockIdx.x * ECHUNK;
    const float* Yb = Y + (long long)b * Dd * 1152;
    float sr0 = 0, si0 = 0, sr1 = 0, si1 = 0, sr2 = 0, si2 = 0;
    #pragma unroll
    for (int e = e0; e < e0 + ECHUNK; e++) {
        const float* w = WkHat + (long long)e * 1026;
        const float* y = Yb + (long long)e * 1152;
        {
            int f = tid;
            float Wr = w[f], Wi = w[513 + f], Yr = y[f], Yi = y[513 + f];
            sr0 += Wr * Yr - Wi * Yi;  si0 += Wr * Yi + Wi * Yr;
        }
        {
            int f = tid + 256;
            float Wr = w[f], Wi = w[513 + f], Yr = y[f], Yi = y[513 + f];
            sr1 += Wr * Yr - Wi * Yi;  si1 += Wr * Yi + Wi * Yr;
        }
        if (tid == 0) {
            int f = 512;
            float Wr = w[f], Wi = w[513 + f], Yr = y[f], Yi = y[513 + f];
            sr2 += Wr * Yr - Wi * Yi;  si2 += Wr * Yi + Wi * Yr;
        }
    }
    float* Sb = S + b * 513 * 2;
    atomicAdd(&Sb[tid * 2 + 0], sr0);        atomicAdd(&Sb[tid * 2 + 1], si0);
    atomicAdd(&Sb[(tid + 256) * 2 + 0], sr1); atomicAdd(&Sb[(tid + 256) * 2 + 1], si1);
    if (tid == 0) { atomicAdd(&Sb[512 * 2 + 0], sr2); atomicAdd(&Sb[512 * 2 + 1], si2); }
}

// ---------------- bias terms: S += bhv*Mk + bhk*Mv + T*bhk*bhv ----------------
__global__ __launch_bounds__(256) void bias_S(
    const float* __restrict__ mk, const float* __restrict__ mv,
    const float* __restrict__ bhat, float* __restrict__ S)
{
    __shared__ float Ar0[1056], Ai0[1056], Ar1[1056], Ai1[1056];
    __shared__ float twr[256], twi[256];
    const int b = blockIdx.x, tid = threadIdx.x;
    {
        float sv, cv;
        __sincosf(-6.28318530717958647692f * (float)tid / 1024.f, &sv, &cv);
        twr[tid] = cv; twi[tid] = sv;
    }
    #pragma unroll
    for (int q = 0; q < 4; q++) {
        int i = tid + 256 * q;
        Ar0[FPAD(i)] = mk[b * Dd + i];
        Ai0[FPAD(i)] = 0.f;
    }
    __syncthreads();
    fft1024_stages(Ar0, Ai0, Ar1, Ai1, twr, twi, tid, 0);
    float Mkr0 = Ar1[FPAD(tid)],       Mki0 = Ai1[FPAD(tid)];
    float Mkr1 = Ar1[FPAD(tid + 256)], Mki1 = Ai1[FPAD(tid + 256)];
    float Mkr2 = 0.f, Mki2 = 0.f;
    if (tid == 0) { Mkr2 = Ar1[FPAD(512)]; Mki2 = Ai1[FPAD(512)]; }
    __syncthreads();
    #pragma unroll
    for (int q = 0; q < 4; q++) {
        int i = tid + 256 * q;
        Ar0[FPAD(i)] = mv[b * Dd + i];
        Ai0[FPAD(i)] = 0.f;
    }
    __syncthreads();
    fft1024_stages(Ar0, Ai0, Ar1, Ai1, twr, twi, tid, 0);
    float Mvr0 = Ar1[FPAD(tid)],       Mvi0 = Ai1[FPAD(tid)];
    float Mvr1 = Ar1[FPAD(tid + 256)], Mvi1 = Ai1[FPAD(tid + 256)];
    float Mvr2 = 0.f, Mvi2 = 0.f;
    if (tid == 0) { Mvr2 = Ar1[FPAD(512)]; Mvi2 = Ai1[FPAD(512)]; }

    auto add = [&](int f, float Mkr, float Mki, float Mvr, float Mvi) {
        float bkr = bhat[f], bki = bhat[513 + f];
        float bvr = bhat[1026 + f], bvi = bhat[1026 + 513 + f];
        float Sr = bvr * Mkr - bvi * Mki + bkr * Mvr - bki * Mvi
                 + (float)Sq * (bkr * bvr - bki * bvi);
        float Si = bvr * Mki + bvi * Mkr + bkr * Mvi + bki * Mvr
                 + (float)Sq * (bkr * bvi + bki * bvr);
        S[b * 1026 + 2 * f]     += Sr;
        S[b * 1026 + 2 * f + 1] += Si;
    };
    add(tid, Mkr0, Mki0, Mvr0, Mvi0);
    add(tid + 256, Mkr1, Mki1, Mvr1, Mvi1);
    if (tid == 0) add(512, Mkr2, Mki2, Mvr2, Mvi2);
}

// ---------------- fft_w2: W2 rows (d<Dd) + r (d==Dd) via spectral unbind ----------------
__global__ __launch_bounds__(256) void fft_w2(
    const float* __restrict__ Wq, const float* __restrict__ bq,
    const float* __restrict__ Sacc,
    __half* __restrict__ W2tmp, float* __restrict__ r)
{
    __shared__ float Ar0[1056], Ai0[1056], Ar1[1056], Ai1[1056];
    __shared__ float twf_r[256], twf_i[256], twb_r[256], twb_i[256];
    const int tid = threadIdx.x;
    const int d = blockIdx.x;
    {
        float sv, cv;
        __sincosf(-6.28318530717958647692f * (float)tid / 1024.f, &sv, &cv);
        twf_r[tid] = cv; twf_i[tid] = sv;
        twb_r[tid] = cv; twb_i[tid] = -sv;
    }
    const float* wrow = (d < Dd) ? (Wq + (long long)d * Dd) : bq;
    #pragma unroll
    for (int q = 0; q < 4; q++) {
        int i = tid + 256 * q;
        Ar0[FPAD(i)] = wrow[i];
        Ai0[FPAD(i)] = 0.f;
    }
    __syncthreads();
    fft1024_stages(Ar0, Ai0, Ar1, Ai1, twf_r, twf_i, tid, 0);

    float Wr[4], Wi[4];
    #pragma unroll
    for (int q = 0; q < 4; q++) {
        int f = tid + 256 * q;
        Wr[q] = Ar1[FPAD(f)];
        Wi[q] = Ai1[FPAD(f)];
    }

    for (int b = 0; b < Bsz; b++) {
        const float* Sb = Sacc + b * 513 * 2;
        #pragma unroll
        for (int q = 0; q < 4; q++) {
            int f = tid + 256 * q;
            float Sr, Si;
            if (f <= 512) { Sr = Sb[f * 2]; Si = Sb[f * 2 + 1]; }
            else          { Sr = Sb[(1024 - f) * 2]; Si = -Sb[(1024 - f) * 2 + 1]; }
            Ar0[FPAD(f)] = Sr * Wr[q] + Si * Wi[q];
            Ai0[FPAD(f)] = Si * Wr[q] - Sr * Wi[q];
        }
        __syncthreads();
        fft1024_stages(Ar0, Ai0, Ar1, Ai1, twb_r, twb_i, tid, 1);
        if (d < Dd) {
            __half* dst = W2tmp + ((long long)b << 20) + ((long long)d << 10);
            #pragma unroll
            for (int q = 0; q < 4; q++) {
                int i = tid + 256 * q;
                dst[i] = __float2half(Ar1[FPAD(i)] * (1.f / 1024.f));
            }
        } else {
            float* dst = r + b * Dd;
            #pragma unroll
            for (int q = 0; q < 4; q++) {
                int i = tid + 256 * q;
                dst[i] = Ar1[FPAD(i)] * (1.f / 1024.f);
            }
        }
    }
}

// ---------------- fused x prep: xh (same layout) + xTh (transposed) + colsum m ----------------
__global__ __launch_bounds__(256) void prep_x(
    const float* __restrict__ x, __half* __restrict__ xh, __half* __restrict__ xTh,
    float* __restrict__ m)
{
    __shared__ __half th[64][65];
    const int b = blockIdx.z;
    const int t0 = blockIdx.y * 64, d0 = blockIdx.x * 64;
    const int tid = threadIdx.x;
    const long long xbase = ((long long)b * Sq + t0) * Dd + d0;
    const int c = tid & 63, rq = tid >> 6;
    float csum = 0.f;
    #pragma unroll
    for (int k = 0; k < 16; k++) {
        int rr = rq + k * 4;
        float v = x[xbase + (long long)rr * Dd + c];
        __half h = __float2half(v);
        xh[xbase + (long long)rr * Dd + c] = h;
        th[rr][c] = h;
        csum += v;
    }
    atomicAdd(&m[b * Dd + d0 + c], csum);
    __syncthreads();
    const long long obase = ((long long)b * Dd + d0) * Sq + t0;
    #pragma unroll
    for (int it = 0; it < 8; it++) {
        int id = tid + it * 256;
        int cc = id >> 5, rp = (id & 31) * 2;
        __half2 v = { th[rp][cc], th[rp + 1][cc] };
        *reinterpret_cast<__half2*>(xTh + obase + (long long)cc * Sq + rp) = v;
    }
}

// ---------------- misc small kernels ----------------
__global__ void zero_all(float* S, float* m, float* mk, float* mv)
{
    int i = blockIdx.x * 256 + threadIdx.x;
    if (i < Bsz * 513 * 2) S[i] = 0.f;
    if (i < Bsz * Dd) { m[i] = 0.f; mk[i] = 0.f; mv[i] = 0.f; }
}

// mk = m@Wk ; mv = m@Wv — e-chunked (16 rows/block), 512 blocks, atomics
__global__ void gemv_mw(const float* __restrict__ Wk, const float* __restrict__ Wv,
                        const float* __restrict__ m,
                        float* __restrict__ mk, float* __restrict__ mv)
{
    int d = blockIdx.x * 256 + threadIdx.x;
    int e0 = blockIdx.z * 16;
    const float* W = blockIdx.y ? Wv : Wk;
    float* o = blockIdx.y ? mv : mk;
    float a0 = 0, a1 = 0, a2 = 0, a3 = 0;
    #pragma unroll
    for (int e = e0; e < e0 + 16; e++) {
        float w = W[(long long)e * Dd + d];
        a0 += m[e] * w;
        a1 += m[Dd + e] * w;
        a2 += m[2 * Dd + e] * w;
        a3 += m[3 * Dd + e] * w;
    }
    atomicAdd(&o[d], a0);
    atomicAdd(&o[Dd + d], a1);
    atomicAdd(&o[2 * Dd + d], a2);
    atomicAdd(&o[3 * Dd + d], a3);
}

__global__ void transpose_f16(const __half* __restrict__ s, __half* __restrict__ d,
                              int R, int C, long long sIn, long long sOut)
{
    __shared__ __half t[64][65];
    int b = blockIdx.z;
    s += (long long)b * sIn; d += (long long)b * sOut;
    int c0 = blockIdx.x * 64, r0 = blockIdx.y * 64;
    int tid = threadIdx.x;
    #pragma unroll
    for (int it = 0; it < 8; it++) {
        int id = tid + it * 256;
        int row = id >> 5, cp = (id & 31) * 2;
        __half2 v = *reinterpret_cast<const __half2*>(s + (long long)(r0 + row) * C + c0 + cp);
        t[row][cp] = v.x; t[row][cp + 1] = v.y;
    }
    __syncthreads();
    #pragma unroll
    for (int it = 0; it < 8; it++) {
        int id = tid + it * 256;
        int cc = id >> 5, rp = (id & 31) * 2;
        __half2 v = { t[rp][cc], t[rp + 1][cc] };
        *reinterpret_cast<__half2*>(d + (long long)(c0 + cc) * R + r0 + rp) = v;
    }
}

// ---------------- launcher ----------------
extern "C" void kernel_launch(void* const* d_in, const int* in_sizes, int n_in,
                              void* d_out, int out_size)
{
    const float* x  = (const float*)d_in[0];
    const float* Wq = (const float*)d_in[1];
    const float* bq = (const float*)d_in[2];
    const float* Wk = (const float*)d_in[3];
    const float* bk = (const float*)d_in[4];
    const float* Wv = (const float*)d_in[5];
    const float* bv = (const float*)d_in[6];
    float* out = (float*)d_out;

    __half *xh, *xTh, *Gh, *WvHatT, *W2tmp, *W2Ts;
    float *WkHat, *bhat, *Y, *m, *mk, *mv, *S, *r;
    cudaGetSymbolAddress((void**)&xh, g_xh);
    cudaGetSymbolAddress((void**)&xTh, g_xTh);
    cudaGetSymbolAddress((void**)&Gh, g_Gh);
    cudaGetSymbolAddress((void**)&WkHat, g_WkHat);
    cudaGetSymbolAddress((void**)&WvHatT, g_WvHatT);
    cudaGetSymbolAddress((void**)&bhat, g_bhat);
    cudaGetSymbolAddress((void**)&Y, g_Y);
    cudaGetSymbolAddress((void**)&m, g_m);
    cudaGetSymbolAddress((void**)&mk, g_mk);
    cudaGetSymbolAddress((void**)&mv, g_mv);
    cudaGetSymbolAddress((void**)&S, g_S);
    cudaGetSymbolAddress((void**)&r, g_r);
    cudaGetSymbolAddress((void**)&W2tmp, g_W2tmp);
    cudaGetSymbolAddress((void**)&W2Ts, g_W2Ts);

    cudaFuncSetAttribute(gemm_hmma, cudaFuncAttributeMaxDynamicSharedMemorySize, DSMEM1);

    const long long dd = (long long)Dd * Dd;        // 1M
    const long long sd = (long long)Sq * Dd;        // 4M

    // 0) zeros; fused x prep (xh + xTh + colsum m); weight row-FFTs (+pad zero)
    zero_all<<<(Bsz * 513 * 2 + 255) / 256, 256>>>(S, m, mk, mv);
    prep_x<<<dim3(Dd / 64, Sq / 64, Bsz), 256>>>(x, xh, xTh, m);
    fft_rows<<<2 * Dd + 2, 256>>>(Wk, Wv, bk, bv, WkHat, WvHatT, bhat);

    // bias path: mk = m@Wk, mv = m@Wv  (512 blocks, latency-covered)
    gemv_mw<<<dim3(Dd / 256, 2, Dd / 16), 256>>>(Wk, Wv, m, mk, mv);

    // 1) Gram: G_b = xT_b @ xT_b^T  (M=N=1024, K=4096) -> fp16
    gemm_hmma<<<dim3(Dd / 128, Dd / 128, Bsz), 128, DSMEM1>>>(
        xTh, xTh, nullptr, nullptr, Gh, Dd, Sq, sd, sd, 0, dd);

    // 2) Y_b = G_b @ WvHat  (N=1152 = 513 Re + 513 Im + pad) -> fp32
    gemm_hmma<<<dim3(1152 / 128, Dd / 128, Bsz), 128, DSMEM1>>>(
        Gh, WvHatT, nullptr, Y, nullptr, 1152, Dd, dd, 0, 0, (long long)Dd * 1152);

    // 3) S[b][f] = sum_e WkHat[e][f] * Y[b][e][f]  (+ bias spectrum terms)
    dot_S<<<dim3(Dd / ECHUNK, Bsz), 256>>>(WkHat, Y, S);
    bias_S<<<Bsz, 256>>>(mk, mv, bhat, S);

    // 4) W2 rows (d<Dd) + r (d==Dd) via spectral unbind; transpose to [n][d]
    fft_w2<<<Dd + 1, 256>>>(Wq, bq, S, W2tmp, r);
    transpose_f16<<<dim3(Dd / 64, Dd / 64, Bsz), 256>>>(W2tmp, W2Ts, Dd, Dd, dd, dd);

    // 5) out_b = x_b @ W2_b + r_b  (fp32 out)
    gemm_hmma<<<dim3(Dd / 128, Sq / 128, Bsz), 128, DSMEM1>>>(
        xh, W2Ts, r, out, nullptr, Dd, Dd, sd, dd, Dd, sd);
}